// round 1
// baseline (speedup 1.0000x reference)
#include <cuda_runtime.h>

// ---------------------------------------------------------------------------
// HiddenRRGCN: 2-layer hetero GraphConv (norm='right'), shared weights.
// Restructure: aggregate RAW features per relation (atomic scatter-add),
// then fused GEMM([n,256]@[256,128]) + bias + LeakyReLU + LayerNorm epilogue.
//   cells: out_c = LN(leaky( (Agc*invdeg_gc)@W_gc + (Acc*invdeg_cc)@W_cc + b_cell ))
//   genes: out_g = LN(leaky( (Acg*invdeg_cg)@W_cg + (Agg*invdeg_gg)@W_gg + b_gene ))
// ---------------------------------------------------------------------------

static constexpr int NCn = 100000;
static constexpr int NGn = 8000;
static constexpr int Dd  = 128;
static constexpr int E_CG = 1500000;
static constexpr int E_GC = 1500000;
static constexpr int E_CC = 1000000;
static constexpr int E_GG = 200000;

// Scratch (static device globals; no runtime allocation).
__device__ __align__(16) float g_Ac[(size_t)NCn * 256];   // [Agc | Acc]
__device__ __align__(16) float g_Ag[(size_t)NGn * 256];   // [Acg | Agg]
__device__ __align__(16) float g_hc1[(size_t)NCn * Dd];
__device__ __align__(16) float g_hg1[(size_t)NGn * Dd];
__device__ int   g_deg[2 * NCn + 2 * NGn];                // [deg_gc | deg_cc | deg_cg | deg_gg]
__device__ float g_inv[2 * NCn + 2 * NGn];

// ---------------------------------------------------------------------------
__global__ void zero_f4(float* __restrict__ p, int n4) {
    int i = blockIdx.x * blockDim.x + threadIdx.x;
    if (i < n4) reinterpret_cast<float4*>(p)[i] = make_float4(0.f, 0.f, 0.f, 0.f);
}

__global__ void zero_i(int* __restrict__ p, int n) {
    int i = blockIdx.x * blockDim.x + threadIdx.x;
    if (i < n) p[i] = 0;
}

__global__ void count_deg(const int* __restrict__ dst, int* __restrict__ deg, int E) {
    int i = blockIdx.x * blockDim.x + threadIdx.x;
    if (i < E) atomicAdd(&deg[dst[i]], 1);
}

__global__ void make_inv(int n) {
    int i = blockIdx.x * blockDim.x + threadIdx.x;
    if (i < n) {
        int d = g_deg[i];
        g_inv[i] = 1.0f / (float)(d > 0 ? d : 1);
    }
}

// One warp per edge: gather 128 floats from h[src], atomic-add into A[dst].
__global__ void scatter_add(const float* __restrict__ h,
                            const int* __restrict__ src,
                            const int* __restrict__ dst,
                            float* __restrict__ A, int E, int colOff) {
    int idx = blockIdx.x * blockDim.x + threadIdx.x;
    int e = idx >> 5;
    int lane = idx & 31;
    if (e >= E) return;
    int s = __ldg(src + e);
    int d = __ldg(dst + e);
    float4 v = __ldg(reinterpret_cast<const float4*>(h + (size_t)s * Dd) + lane);
    float* p = A + (size_t)d * 256 + colOff + lane * 4;
    atomicAdd(p + 0, v.x);
    atomicAdd(p + 1, v.y);
    atomicAdd(p + 2, v.z);
    atomicAdd(p + 3, v.w);
}

// ---------------------------------------------------------------------------
// Fused GEMM + bias + LeakyReLU + LayerNorm.
// X = [A(:,0:128)*invA , A(:,128:256)*invB]  (row-scaled on load)
// out[r,:] = LN(leaky(X[r,:] @ [Wa;Wb] + bias)) * lns + lnb
// Block: 128 rows x 128 cols, 256 threads, 8x8 register tile per thread.
// Dynamic smem: Ws [256][128] (128 KB) + Xs [32][132] (~17 KB).
// ---------------------------------------------------------------------------
static constexpr int GEMM_SMEM = (256 * 128 + 32 * 132) * (int)sizeof(float);

extern "C" __global__ void __launch_bounds__(256, 1)
gemm_ln(const float* __restrict__ A,
        const float* __restrict__ invA, const float* __restrict__ invB,
        const float* __restrict__ Wa, const float* __restrict__ Wb,
        const float* __restrict__ bias,
        const float* __restrict__ lns, const float* __restrict__ lnb,
        float* __restrict__ out, int n) {
    extern __shared__ float smem[];
    float* Ws = smem;               // [256][128]
    float* Xs = smem + 256 * 128;   // [32][132]

    const int tid = threadIdx.x;
    const int tx = tid & 15;        // col group
    const int ty = tid >> 4;        // row group
    const int row0 = blockIdx.x * 128;

    // Load both W halves into smem (each [128,128], contiguous copy).
    {
        float4* ws4 = reinterpret_cast<float4*>(Ws);
        const float4* wa4 = reinterpret_cast<const float4*>(Wa);
        const float4* wb4 = reinterpret_cast<const float4*>(Wb);
#pragma unroll
        for (int i = 0; i < 16; ++i) ws4[tid + i * 256] = __ldg(wa4 + tid + i * 256);
#pragma unroll
        for (int i = 0; i < 16; ++i) ws4[4096 + tid + i * 256] = __ldg(wb4 + tid + i * 256);
    }

    float acc[8][8];
#pragma unroll
    for (int i = 0; i < 8; ++i)
#pragma unroll
        for (int j = 0; j < 8; ++j) acc[i][j] = 0.f;

    for (int k0 = 0; k0 < 256; k0 += 32) {
        __syncthreads();   // covers initial W load & previous Xs consumption
        // Load X tile transposed: Xs[k][row], row-scaled by inv-degree.
#pragma unroll
        for (int pass = 0; pass < 4; ++pass) {
            int r = (tid >> 3) + pass * 32;
            int kq = (tid & 7) << 2;
            int grow = row0 + r;
            float4 v = make_float4(0.f, 0.f, 0.f, 0.f);
            float sc = 0.f;
            if (grow < n) {
                v = __ldg(reinterpret_cast<const float4*>(A + (size_t)grow * 256 + k0) + (tid & 7));
                sc = (k0 < 128) ? __ldg(invA + grow) : __ldg(invB + grow);
            }
            Xs[(kq + 0) * 132 + r] = v.x * sc;
            Xs[(kq + 1) * 132 + r] = v.y * sc;
            Xs[(kq + 2) * 132 + r] = v.z * sc;
            Xs[(kq + 3) * 132 + r] = v.w * sc;
        }
        __syncthreads();

#pragma unroll
        for (int kk = 0; kk < 32; ++kk) {
            float4 a0 = *reinterpret_cast<const float4*>(&Xs[kk * 132 + ty * 4]);
            float4 a1 = *reinterpret_cast<const float4*>(&Xs[kk * 132 + 64 + ty * 4]);
            float4 b0 = *reinterpret_cast<const float4*>(&Ws[(k0 + kk) * 128 + tx * 4]);
            float4 b1 = *reinterpret_cast<const float4*>(&Ws[(k0 + kk) * 128 + 64 + tx * 4]);
            float a[8] = {a0.x, a0.y, a0.z, a0.w, a1.x, a1.y, a1.z, a1.w};
            float b[8] = {b0.x, b0.y, b0.z, b0.w, b1.x, b1.y, b1.z, b1.w};
#pragma unroll
            for (int i = 0; i < 8; ++i)
#pragma unroll
                for (int j = 0; j < 8; ++j) acc[i][j] += a[i] * b[j];
        }
    }

    // Epilogue: bias + leaky + per-row LayerNorm (row owned by 16 lanes, shfl w16).
    const int c0 = tx * 4;
    float4 bv0 = __ldg(reinterpret_cast<const float4*>(bias + c0));
    float4 bv1 = __ldg(reinterpret_cast<const float4*>(bias + 64 + c0));
    float4 sv0 = __ldg(reinterpret_cast<const float4*>(lns + c0));
    float4 sv1 = __ldg(reinterpret_cast<const float4*>(lns + 64 + c0));
    float4 ov0 = __ldg(reinterpret_cast<const float4*>(lnb + c0));
    float4 ov1 = __ldg(reinterpret_cast<const float4*>(lnb + 64 + c0));
    float bvs[8] = {bv0.x, bv0.y, bv0.z, bv0.w, bv1.x, bv1.y, bv1.z, bv1.w};
    float svs[8] = {sv0.x, sv0.y, sv0.z, sv0.w, sv1.x, sv1.y, sv1.z, sv1.w};
    float ovs[8] = {ov0.x, ov0.y, ov0.z, ov0.w, ov1.x, ov1.y, ov1.z, ov1.w};

#pragma unroll
    for (int ri = 0; ri < 8; ++ri) {
        int row = row0 + ((ri < 4) ? (ty * 4 + ri) : (64 + ty * 4 + ri - 4));
        float x[8];
        float s = 0.f, s2 = 0.f;
#pragma unroll
        for (int j = 0; j < 8; ++j) {
            float v = acc[ri][j] + bvs[j];
            v = (v >= 0.f) ? v : 0.05f * v;
            x[j] = v;
            s += v;
            s2 += v * v;
        }
#pragma unroll
        for (int o = 1; o < 16; o <<= 1) {
            s  += __shfl_xor_sync(0xffffffffu, s,  o, 16);
            s2 += __shfl_xor_sync(0xffffffffu, s2, o, 16);
        }
        float mean = s * (1.f / 128.f);
        float var = s2 * (1.f / 128.f) - mean * mean;
        float rstd = rsqrtf(var + 1e-5f);
        if (row < n) {
            float y[8];
#pragma unroll
            for (int j = 0; j < 8; ++j) y[j] = (x[j] - mean) * rstd * svs[j] + ovs[j];
            float* op = out + (size_t)row * 128;
            *reinterpret_cast<float4*>(op + c0)      = make_float4(y[0], y[1], y[2], y[3]);
            *reinterpret_cast<float4*>(op + 64 + c0) = make_float4(y[4], y[5], y[6], y[7]);
        }
    }
}

// ---------------------------------------------------------------------------
extern "C" void kernel_launch(void* const* d_in, const int* in_sizes, int n_in,
                              void* d_out, int out_size) {
    const float* h_cell = (const float*)d_in[0];
    const float* h_gene = (const float*)d_in[1];
    const int* src_cg = (const int*)d_in[2];
    const int* dst_cg = (const int*)d_in[3];
    const int* src_gc = (const int*)d_in[4];
    const int* dst_gc = (const int*)d_in[5];
    const int* src_cc = (const int*)d_in[6];
    const int* dst_cc = (const int*)d_in[7];
    const int* src_gg = (const int*)d_in[8];
    const int* dst_gg = (const int*)d_in[9];
    const float* W_cg = (const float*)d_in[10];
    const float* W_gc = (const float*)d_in[11];
    const float* W_cc = (const float*)d_in[12];
    const float* W_gg = (const float*)d_in[13];
    const float* b_cell = (const float*)d_in[14];
    const float* b_gene = (const float*)d_in[15];
    const float* ln_s_cell = (const float*)d_in[16];
    const float* ln_b_cell = (const float*)d_in[17];
    const float* ln_s_gene = (const float*)d_in[18];
    const float* ln_b_gene = (const float*)d_in[19];
    float* out = (float*)d_out;

    float *Ac, *Ag, *hc1, *hg1, *inv;
    int* deg;
    cudaGetSymbolAddress((void**)&Ac, g_Ac);
    cudaGetSymbolAddress((void**)&Ag, g_Ag);
    cudaGetSymbolAddress((void**)&hc1, g_hc1);
    cudaGetSymbolAddress((void**)&hg1, g_hg1);
    cudaGetSymbolAddress((void**)&deg, g_deg);
    cudaGetSymbolAddress((void**)&inv, g_inv);

    cudaFuncSetAttribute(gemm_ln, cudaFuncAttributeMaxDynamicSharedMemorySize, GEMM_SMEM);

    const int NDEG = 2 * NCn + 2 * NGn;

    // Per-relation in-degree -> inverse (shared by both layers).
    zero_i<<<(NDEG + 255) / 256, 256>>>(deg, NDEG);
    count_deg<<<(E_GC + 255) / 256, 256>>>(dst_gc, deg + 0, E_GC);
    count_deg<<<(E_CC + 255) / 256, 256>>>(dst_cc, deg + NCn, E_CC);
    count_deg<<<(E_CG + 255) / 256, 256>>>(dst_cg, deg + 2 * NCn, E_CG);
    count_deg<<<(E_GG + 255) / 256, 256>>>(dst_gg, deg + 2 * NCn + NGn, E_GG);
    make_inv<<<(NDEG + 255) / 256, 256>>>(NDEG);

    const float* inv_gc = inv + 0;
    const float* inv_cc = inv + NCn;
    const float* inv_cg = inv + 2 * NCn;
    const float* inv_gg = inv + 2 * NCn + NGn;

    auto run_layer = [&](const float* hc, const float* hg, float* oc, float* og) {
        zero_f4<<<(NCn * 64 + 255) / 256, 256>>>(Ac, NCn * 64);
        zero_f4<<<(NGn * 64 + 255) / 256, 256>>>(Ag, NGn * 64);
        // Edge scatter: 1 warp / edge.
        scatter_add<<<(E_GC * 32 + 255) / 256, 256>>>(hg, src_gc, dst_gc, Ac, E_GC, 0);
        scatter_add<<<(E_CC * 32 + 255) / 256, 256>>>(hc, src_cc, dst_cc, Ac, E_CC, 128);
        scatter_add<<<(E_CG * 32 + 255) / 256, 256>>>(hc, src_cg, dst_cg, Ag, E_CG, 0);
        scatter_add<<<(E_GG * 32 + 255) / 256, 256>>>(hg, src_gg, dst_gg, Ag, E_GG, 128);
        // Fused GEMM + bias + leaky + LN.
        gemm_ln<<<(NCn + 127) / 128, 256, GEMM_SMEM>>>(
            Ac, inv_gc, inv_cc, W_gc, W_cc, b_cell, ln_s_cell, ln_b_cell, oc, NCn);
        gemm_ln<<<(NGn + 127) / 128, 256, GEMM_SMEM>>>(
            Ag, inv_cg, inv_gg, W_cg, W_gg, b_gene, ln_s_gene, ln_b_gene, og, NGn);
    };

    // Layer 1 -> scratch, Layer 2 -> output (cells then genes).
    run_layer(h_cell, h_gene, hc1, hg1);
    run_layer(hc1, hg1, out, out + (size_t)NCn * Dd);

    (void)in_sizes; (void)n_in; (void)out_size;
}

// round 2
// speedup vs baseline: 1.9270x; 1.9270x over previous
#include <cuda_runtime.h>

// ---------------------------------------------------------------------------
// HiddenRRGCN: 2-layer hetero GraphConv (norm='right'), shared weights.
// Round 2: CSR gather (no feature atomics) fused with GEMM+bias+leaky+LN.
//   out_dst = LN(leaky( (csrA-mean(hA))@WA + (csrB-mean(hB))@WB + bias ))
// ---------------------------------------------------------------------------

static constexpr int NCn = 100000;
static constexpr int NGn = 8000;
static constexpr int E_CG = 1500000;
static constexpr int E_GC = 1500000;
static constexpr int E_CC = 1000000;
static constexpr int E_GG = 200000;

// ---- static scratch -------------------------------------------------------
__device__ int   g_deg[2 * NCn + 2 * NGn];   // [gc | cc | cg | gg]
__device__ float g_inv[2 * NCn + 2 * NGn];
__device__ int   g_cur[2 * NCn + 2 * NGn];
__device__ int   g_rp_gc[NCn + 1];
__device__ int   g_rp_cc[NCn + 1];
__device__ int   g_rp_cg[NGn + 1];
__device__ int   g_rp_gg[NGn + 1];
__device__ int   g_col_gc[E_GC];
__device__ int   g_col_cc[E_CC];
__device__ int   g_col_cg[E_CG];
__device__ int   g_col_gg[E_GG];
__device__ __align__(16) float g_hc1[(size_t)NCn * 128];
__device__ __align__(16) float g_hg1[(size_t)NGn * 128];

// ---------------------------------------------------------------------------
__global__ void zero_i(int* __restrict__ p, int n) {
    int i = blockIdx.x * blockDim.x + threadIdx.x;
    if (i < n) p[i] = 0;
}

__global__ void count_deg(const int* __restrict__ dst, int* __restrict__ deg, int E) {
    int i = blockIdx.x * blockDim.x + threadIdx.x;
    if (i < E) atomicAdd(&deg[dst[i]], 1);
}

__global__ void make_inv(int n) {
    int i = blockIdx.x * blockDim.x + threadIdx.x;
    if (i < n) {
        int d = g_deg[i];
        g_inv[i] = 1.0f / (float)(d > 0 ? d : 1);
    }
}

// Single-block exclusive scan (n up to a few 100K; runs once, trivial time).
__global__ void exscan(const int* __restrict__ in, int* __restrict__ out, int n) {
    __shared__ int wsum[32];
    __shared__ int carry_s;
    const int tid = threadIdx.x;
    if (tid == 0) carry_s = 0;
    __syncthreads();
    for (int base = 0; base < n; base += 1024) {
        int i = base + tid;
        int v = (i < n) ? in[i] : 0;
        int x = v;
#pragma unroll
        for (int o = 1; o < 32; o <<= 1) {
            int t = __shfl_up_sync(0xffffffffu, x, o);
            if ((tid & 31) >= o) x += t;
        }
        if ((tid & 31) == 31) wsum[tid >> 5] = x;
        __syncthreads();
        if (tid < 32) {
            int s = wsum[tid];
#pragma unroll
            for (int o = 1; o < 32; o <<= 1) {
                int t = __shfl_up_sync(0xffffffffu, s, o);
                if (tid >= o) s += t;
            }
            wsum[tid] = s;
        }
        __syncthreads();
        int woff = (tid >= 32) ? wsum[(tid >> 5) - 1] : 0;
        int incl = x + woff + carry_s;
        if (i < n) out[i] = incl - v;
        __syncthreads();
        if (tid == 1023) carry_s = incl;
        __syncthreads();
    }
    if (tid == 0) out[n] = carry_s;
}

__global__ void init_cursor(const int* __restrict__ rp, int* __restrict__ cur, int n) {
    int i = blockIdx.x * blockDim.x + threadIdx.x;
    if (i < n) cur[i] = rp[i];
}

__global__ void fill_csr(const int* __restrict__ src, const int* __restrict__ dst,
                         int* __restrict__ cur, int* __restrict__ col, int E) {
    int i = blockIdx.x * blockDim.x + threadIdx.x;
    if (i < E) {
        int d = dst[i];
        int pos = atomicAdd(&cur[d], 1);
        col[pos] = src[i];
    }
}

// ---------------------------------------------------------------------------
// Fused: CSR-gather aggregation (both relations) + GEMM + bias + leaky + LN.
// Block: TM rows x 128 cols, 256 threads.
// Smem: Xs[TM][132] (holds one 128-wide K half) + Wt[2][32][128] ping-pong.
// ---------------------------------------------------------------------------
template <int TM>
__device__ __forceinline__ int row_of(int ty, int i) {
    if (TM == 128) return (i < 4) ? (ty * 4 + i) : (64 + ty * 4 + (i - 4));
    return ty * (TM / 16) + i;
}

template <int TM>
__global__ void __launch_bounds__(256)
fused_layer(const int* __restrict__ rpA, const int* __restrict__ colA,
            const float* __restrict__ hA, const float* __restrict__ invA,
            const float* __restrict__ WA,
            const int* __restrict__ rpB, const int* __restrict__ colB,
            const float* __restrict__ hB, const float* __restrict__ invB,
            const float* __restrict__ WB,
            const float* __restrict__ bias,
            const float* __restrict__ lns, const float* __restrict__ lnb,
            float* __restrict__ out, int n) {
    constexpr int RPT = TM / 16;  // rows per thread (8 or 2)
    extern __shared__ float smem[];
    float* Xs = smem;                    // [TM][132]
    float* Wt = smem + TM * 132;         // [2][32*128]

    const int tid = threadIdx.x;
    const int lane = tid & 31;
    const int wid = tid >> 5;
    const int tx = tid & 15;
    const int ty = tid >> 4;
    const int row0 = blockIdx.x * TM;

    float acc[RPT][8];
#pragma unroll
    for (int i = 0; i < RPT; ++i)
#pragma unroll
        for (int j = 0; j < 8; ++j) acc[i][j] = 0.f;

#pragma unroll
    for (int half = 0; half < 2; ++half) {
        const int* rp = half ? rpB : rpA;
        const int* col = half ? colB : colA;
        const float4* hp = reinterpret_cast<const float4*>(half ? hB : hA);
        const float* invp = half ? invB : invA;
        const float4* W4 = reinterpret_cast<const float4*>(half ? WB : WA);

        // Prefetch W tile 0 of this half while we aggregate.
        float4 wreg[4];
#pragma unroll
        for (int i = 0; i < 4; ++i) wreg[i] = __ldg(W4 + tid + i * 256);

        // ---- aggregation: warp per row, lane holds 4 of 128 features ----
        for (int r = wid; r < TM; r += 8) {
            int row = row0 + r;
            float4 a0 = make_float4(0.f, 0.f, 0.f, 0.f);
            float4 a1 = a0, a2 = a0, a3 = a0;
            float sc = 0.f;
            if (row < n) {
                int e = __ldg(rp + row);
                int eEnd = __ldg(rp + row + 1);
                sc = __ldg(invp + row);
                for (; e + 4 <= eEnd; e += 4) {
                    int s0 = __ldg(col + e);
                    int s1 = __ldg(col + e + 1);
                    int s2 = __ldg(col + e + 2);
                    int s3 = __ldg(col + e + 3);
                    float4 v0 = __ldg(hp + (size_t)s0 * 32 + lane);
                    float4 v1 = __ldg(hp + (size_t)s1 * 32 + lane);
                    float4 v2 = __ldg(hp + (size_t)s2 * 32 + lane);
                    float4 v3 = __ldg(hp + (size_t)s3 * 32 + lane);
                    a0.x += v0.x; a0.y += v0.y; a0.z += v0.z; a0.w += v0.w;
                    a1.x += v1.x; a1.y += v1.y; a1.z += v1.z; a1.w += v1.w;
                    a2.x += v2.x; a2.y += v2.y; a2.z += v2.z; a2.w += v2.w;
                    a3.x += v3.x; a3.y += v3.y; a3.z += v3.z; a3.w += v3.w;
                }
                for (; e < eEnd; ++e) {
                    int s = __ldg(col + e);
                    float4 v = __ldg(hp + (size_t)s * 32 + lane);
                    a0.x += v.x; a0.y += v.y; a0.z += v.z; a0.w += v.w;
                }
            }
            float4 res = make_float4((a0.x + a1.x + a2.x + a3.x) * sc,
                                     (a0.y + a1.y + a2.y + a3.y) * sc,
                                     (a0.z + a1.z + a2.z + a3.z) * sc,
                                     (a0.w + a1.w + a2.w + a3.w) * sc);
            *reinterpret_cast<float4*>(&Xs[r * 132 + lane * 4]) = res;
        }

        // ---- GEMM over this half's 128 K values, 4 tiles of 32 ----
#pragma unroll
        for (int kt = 0; kt < 4; ++kt) {
            float* Wb = Wt + (kt & 1) * (32 * 128);
#pragma unroll
            for (int i = 0; i < 4; ++i)
                reinterpret_cast<float4*>(Wb)[tid + i * 256] = wreg[i];
            if (kt < 3) {
#pragma unroll
                for (int i = 0; i < 4; ++i)
                    wreg[i] = __ldg(W4 + (kt + 1) * 1024 + tid + i * 256);
            }
            __syncthreads();   // Wb stored (and, for kt=0, Xs fully aggregated)
#pragma unroll
            for (int kq = 0; kq < 32; kq += 4) {
                float4 av[RPT];
#pragma unroll
                for (int i = 0; i < RPT; ++i) {
                    int r = row_of<TM>(ty, i);
                    av[i] = *reinterpret_cast<const float4*>(&Xs[r * 132 + kt * 32 + kq]);
                }
#pragma unroll
                for (int j4 = 0; j4 < 4; ++j4) {
                    float4 b0 = *reinterpret_cast<const float4*>(&Wb[(kq + j4) * 128 + tx * 4]);
                    float4 b1 = *reinterpret_cast<const float4*>(&Wb[(kq + j4) * 128 + 64 + tx * 4]);
                    float b[8] = {b0.x, b0.y, b0.z, b0.w, b1.x, b1.y, b1.z, b1.w};
#pragma unroll
                    for (int i = 0; i < RPT; ++i) {
                        float a = (j4 == 0) ? av[i].x : (j4 == 1) ? av[i].y
                                  : (j4 == 2) ? av[i].z : av[i].w;
#pragma unroll
                        for (int j = 0; j < 8; ++j) acc[i][j] += a * b[j];
                    }
                }
            }
            __syncthreads();   // all reads of Wb/Xs for this tile done
        }
    }

    // ---- epilogue: bias + leaky + row LayerNorm (16 lanes per row) ----
    const int c0 = tx * 4;
    float4 bv0 = __ldg(reinterpret_cast<const float4*>(bias + c0));
    float4 bv1 = __ldg(reinterpret_cast<const float4*>(bias + 64 + c0));
    float4 sv0 = __ldg(reinterpret_cast<const float4*>(lns + c0));
    float4 sv1 = __ldg(reinterpret_cast<const float4*>(lns + 64 + c0));
    float4 ov0 = __ldg(reinterpret_cast<const float4*>(lnb + c0));
    float4 ov1 = __ldg(reinterpret_cast<const float4*>(lnb + 64 + c0));
    float bvs[8] = {bv0.x, bv0.y, bv0.z, bv0.w, bv1.x, bv1.y, bv1.z, bv1.w};
    float svs[8] = {sv0.x, sv0.y, sv0.z, sv0.w, sv1.x, sv1.y, sv1.z, sv1.w};
    float ovs[8] = {ov0.x, ov0.y, ov0.z, ov0.w, ov1.x, ov1.y, ov1.z, ov1.w};

#pragma unroll
    for (int ri = 0; ri < RPT; ++ri) {
        int row = row0 + row_of<TM>(ty, ri);
        float x[8];
        float s = 0.f, s2 = 0.f;
#pragma unroll
        for (int j = 0; j < 8; ++j) {
            float v = acc[ri][j] + bvs[j];
            v = (v >= 0.f) ? v : 0.05f * v;
            x[j] = v;
            s += v;
            s2 += v * v;
        }
#pragma unroll
        for (int o = 1; o < 16; o <<= 1) {
            s  += __shfl_xor_sync(0xffffffffu, s,  o, 16);
            s2 += __shfl_xor_sync(0xffffffffu, s2, o, 16);
        }
        float mean = s * (1.f / 128.f);
        float var = s2 * (1.f / 128.f) - mean * mean;
        float rstd = rsqrtf(var + 1e-5f);
        if (row < n) {
            float y[8];
#pragma unroll
            for (int j = 0; j < 8; ++j) y[j] = (x[j] - mean) * rstd * svs[j] + ovs[j];
            float* op = out + (size_t)row * 128;
            *reinterpret_cast<float4*>(op + c0)      = make_float4(y[0], y[1], y[2], y[3]);
            *reinterpret_cast<float4*>(op + 64 + c0) = make_float4(y[4], y[5], y[6], y[7]);
        }
    }
}

// ---------------------------------------------------------------------------
extern "C" void kernel_launch(void* const* d_in, const int* in_sizes, int n_in,
                              void* d_out, int out_size) {
    const float* h_cell = (const float*)d_in[0];
    const float* h_gene = (const float*)d_in[1];
    const int* src_cg = (const int*)d_in[2];
    const int* dst_cg = (const int*)d_in[3];
    const int* src_gc = (const int*)d_in[4];
    const int* dst_gc = (const int*)d_in[5];
    const int* src_cc = (const int*)d_in[6];
    const int* dst_cc = (const int*)d_in[7];
    const int* src_gg = (const int*)d_in[8];
    const int* dst_gg = (const int*)d_in[9];
    const float* W_cg = (const float*)d_in[10];
    const float* W_gc = (const float*)d_in[11];
    const float* W_cc = (const float*)d_in[12];
    const float* W_gg = (const float*)d_in[13];
    const float* b_cell = (const float*)d_in[14];
    const float* b_gene = (const float*)d_in[15];
    const float* ln_s_cell = (const float*)d_in[16];
    const float* ln_b_cell = (const float*)d_in[17];
    const float* ln_s_gene = (const float*)d_in[18];
    const float* ln_b_gene = (const float*)d_in[19];
    float* out = (float*)d_out;

    int *deg, *cur, *rp_gc, *rp_cc, *rp_cg, *rp_gg;
    int *col_gc, *col_cc, *col_cg, *col_gg;
    float *inv, *hc1, *hg1;
    cudaGetSymbolAddress((void**)&deg, g_deg);
    cudaGetSymbolAddress((void**)&cur, g_cur);
    cudaGetSymbolAddress((void**)&inv, g_inv);
    cudaGetSymbolAddress((void**)&rp_gc, g_rp_gc);
    cudaGetSymbolAddress((void**)&rp_cc, g_rp_cc);
    cudaGetSymbolAddress((void**)&rp_cg, g_rp_cg);
    cudaGetSymbolAddress((void**)&rp_gg, g_rp_gg);
    cudaGetSymbolAddress((void**)&col_gc, g_col_gc);
    cudaGetSymbolAddress((void**)&col_cc, g_col_cc);
    cudaGetSymbolAddress((void**)&col_cg, g_col_cg);
    cudaGetSymbolAddress((void**)&col_gg, g_col_gg);
    cudaGetSymbolAddress((void**)&hc1, g_hc1);
    cudaGetSymbolAddress((void**)&hg1, g_hg1);

    const int SMEM_C = (128 * 132 + 2 * 32 * 128) * (int)sizeof(float);
    const int SMEM_G = (32 * 132 + 2 * 32 * 128) * (int)sizeof(float);
    cudaFuncSetAttribute(fused_layer<128>, cudaFuncAttributeMaxDynamicSharedMemorySize, SMEM_C);
    cudaFuncSetAttribute(fused_layer<32>,  cudaFuncAttributeMaxDynamicSharedMemorySize, SMEM_G);

    const int NDEG = 2 * NCn + 2 * NGn;

    // ---- CSR build (shared by both layers) ----
    zero_i<<<(NDEG + 255) / 256, 256>>>(deg, NDEG);
    count_deg<<<(E_GC + 255) / 256, 256>>>(dst_gc, deg + 0, E_GC);
    count_deg<<<(E_CC + 255) / 256, 256>>>(dst_cc, deg + NCn, E_CC);
    count_deg<<<(E_CG + 255) / 256, 256>>>(dst_cg, deg + 2 * NCn, E_CG);
    count_deg<<<(E_GG + 255) / 256, 256>>>(dst_gg, deg + 2 * NCn + NGn, E_GG);
    make_inv<<<(NDEG + 255) / 256, 256>>>(NDEG);

    exscan<<<1, 1024>>>(deg + 0,            rp_gc, NCn);
    exscan<<<1, 1024>>>(deg + NCn,          rp_cc, NCn);
    exscan<<<1, 1024>>>(deg + 2 * NCn,      rp_cg, NGn);
    exscan<<<1, 1024>>>(deg + 2 * NCn + NGn, rp_gg, NGn);

    init_cursor<<<(NCn + 255) / 256, 256>>>(rp_gc, cur + 0, NCn);
    init_cursor<<<(NCn + 255) / 256, 256>>>(rp_cc, cur + NCn, NCn);
    init_cursor<<<(NGn + 255) / 256, 256>>>(rp_cg, cur + 2 * NCn, NGn);
    init_cursor<<<(NGn + 255) / 256, 256>>>(rp_gg, cur + 2 * NCn + NGn, NGn);

    fill_csr<<<(E_GC + 255) / 256, 256>>>(src_gc, dst_gc, cur + 0, col_gc, E_GC);
    fill_csr<<<(E_CC + 255) / 256, 256>>>(src_cc, dst_cc, cur + NCn, col_cc, E_CC);
    fill_csr<<<(E_CG + 255) / 256, 256>>>(src_cg, dst_cg, cur + 2 * NCn, col_cg, E_CG);
    fill_csr<<<(E_GG + 255) / 256, 256>>>(src_gg, dst_gg, cur + 2 * NCn + NGn, col_gg, E_GG);

    const float* inv_gc = inv + 0;
    const float* inv_cc = inv + NCn;
    const float* inv_cg = inv + 2 * NCn;
    const float* inv_gg = inv + 2 * NCn + NGn;

    auto run_layer = [&](const float* hc, const float* hg, float* oc, float* og) {
        fused_layer<128><<<(NCn + 127) / 128, 256, SMEM_C>>>(
            rp_gc, col_gc, hg, inv_gc, W_gc,
            rp_cc, col_cc, hc, inv_cc, W_cc,
            b_cell, ln_s_cell, ln_b_cell, oc, NCn);
        fused_layer<32><<<(NGn + 31) / 32, 256, SMEM_G>>>(
            rp_cg, col_cg, hc, inv_cg, W_cg,
            rp_gg, col_gg, hg, inv_gg, W_gg,
            b_gene, ln_s_gene, ln_b_gene, og, NGn);
    };

    run_layer(h_cell, h_gene, hc1, hg1);
    run_layer(hc1, hg1, out, out + (size_t)NCn * 128);

    (void)in_sizes; (void)n_in; (void)out_size;
}

// round 4
// speedup vs baseline: 3.6446x; 1.8913x over previous
#include <cuda_runtime.h>
#include <cuda_bf16.h>
#include <cstdint>

// ---------------------------------------------------------------------------
// HiddenRRGCN: 2-layer hetero GraphConv (norm='right'), shared weights.
// Round 4: CSR gather fused with bf16-split tensor-core GEMM (mma.m16n8k16),
// 3-term split (hi*hi + hi*lo + lo*hi) for fp32-grade accuracy.
// ---------------------------------------------------------------------------

static constexpr int NCn = 100000;
static constexpr int NGn = 8000;
static constexpr int E_CG = 1500000;
static constexpr int E_GC = 1500000;
static constexpr int E_CC = 1000000;
static constexpr int E_GG = 200000;
static constexpr int NDEG = 2 * NCn + 2 * NGn;       // 216000
static constexpr int E_ALL = E_CG + E_GC + E_CC + E_GG;

static constexpr int OFF_GC = 0;
static constexpr int OFF_CC = NCn;
static constexpr int OFF_CG = 2 * NCn;
static constexpr int OFF_GG = 2 * NCn + NGn;

// ---- static scratch -------------------------------------------------------
__device__ int   g_deg[NDEG];
__device__ float g_inv[NDEG];
__device__ int   g_cur[NDEG];
__device__ int   g_rp[NDEG + 1];
__device__ int   g_col[E_ALL];
__device__ int   g_bsum[256];
__device__ int   g_bscan[257];
__device__ __align__(16) float g_hc1[(size_t)NCn * 128];
__device__ __align__(16) float g_hg1[(size_t)NGn * 128];
__device__ __align__(16) __nv_bfloat16 g_Whi[4][128 * 128];  // gc, cc, cg, gg
__device__ __align__(16) __nv_bfloat16 g_Wlo[4][128 * 128];

// ---------------------------------------------------------------------------
__global__ void zero_i(int* __restrict__ p, int n) {
    int i = blockIdx.x * blockDim.x + threadIdx.x;
    if (i < n) p[i] = 0;
}

__global__ void count_deg(const int* __restrict__ dst, int* __restrict__ deg, int E) {
    int i = blockIdx.x * blockDim.x + threadIdx.x;
    if (i < E) atomicAdd(&deg[dst[i]], 1);
}

__global__ void make_inv(int n) {
    int i = blockIdx.x * blockDim.x + threadIdx.x;
    if (i < n) {
        int d = g_deg[i];
        g_inv[i] = 1.0f / (float)(d > 0 ? d : 1);
    }
}

__global__ void convert_w(const float* __restrict__ W,
                          __nv_bfloat16* __restrict__ hi,
                          __nv_bfloat16* __restrict__ lo) {
    int i = blockIdx.x * blockDim.x + threadIdx.x;
    if (i < 128 * 128) {
        float v = W[i];
        __nv_bfloat16 h = __float2bfloat16_rn(v);
        hi[i] = h;
        lo[i] = __float2bfloat16_rn(v - __bfloat162float(h));
    }
}

// ---- multi-block exclusive scan over g_deg -> g_rp ----
__global__ void scan_part1(const int* __restrict__ in, int* __restrict__ bsum, int n) {
    __shared__ int ws[32];
    int tid = threadIdx.x;
    int i = blockIdx.x * 1024 + tid;
    int v = (i < n) ? in[i] : 0;
#pragma unroll
    for (int o = 16; o > 0; o >>= 1) v += __shfl_xor_sync(0xffffffffu, v, o);
    if ((tid & 31) == 0) ws[tid >> 5] = v;
    __syncthreads();
    if (tid < 32) {
        int s = (tid < 32) ? ws[tid] : 0;
#pragma unroll
        for (int o = 16; o > 0; o >>= 1) s += __shfl_xor_sync(0xffffffffu, s, o);
        if (tid == 0) bsum[blockIdx.x] = s;
    }
}

// Single-block exclusive scan (for the per-block sums; nb <= 1024).
__global__ void exscan_small(const int* __restrict__ in, int* __restrict__ out, int n) {
    __shared__ int ws[32];
    int tid = threadIdx.x;
    int v = (tid < n) ? in[tid] : 0;
    int x = v;
#pragma unroll
    for (int o = 1; o < 32; o <<= 1) {
        int t = __shfl_up_sync(0xffffffffu, x, o);
        if ((tid & 31) >= o) x += t;
    }
    if ((tid & 31) == 31) ws[tid >> 5] = x;
    __syncthreads();
    if (tid < 32) {
        int s = ws[tid];
#pragma unroll
        for (int o = 1; o < 32; o <<= 1) {
            int t = __shfl_up_sync(0xffffffffu, s, o);
            if (tid >= o) s += t;
        }
        ws[tid] = s;
    }
    __syncthreads();
    int woff = (tid >= 32) ? ws[(tid >> 5) - 1] : 0;
    if (tid < n) out[tid] = x - v + woff;
    if (tid == n - 1) out[n] = x + woff;
}

__global__ void scan_part3(const int* __restrict__ in, const int* __restrict__ boff,
                           int* __restrict__ out, int n) {
    __shared__ int ws[32];
    int tid = threadIdx.x;
    int i = blockIdx.x * 1024 + tid;
    int v = (i < n) ? in[i] : 0;
    int x = v;
#pragma unroll
    for (int o = 1; o < 32; o <<= 1) {
        int t = __shfl_up_sync(0xffffffffu, x, o);
        if ((tid & 31) >= o) x += t;
    }
    if ((tid & 31) == 31) ws[tid >> 5] = x;
    __syncthreads();
    if (tid < 32) {
        int s = ws[tid];
#pragma unroll
        for (int o = 1; o < 32; o <<= 1) {
            int t = __shfl_up_sync(0xffffffffu, s, o);
            if (tid >= o) s += t;
        }
        ws[tid] = s;
    }
    __syncthreads();
    int woff = ((tid >> 5) > 0) ? ws[(tid >> 5) - 1] : 0;
    int excl = x - v + woff + boff[blockIdx.x];
    if (i < n) out[i] = excl;
    if (i == n - 1) out[n] = excl + v;
}

__global__ void init_cursor(const int* __restrict__ rp, int* __restrict__ cur, int n) {
    int i = blockIdx.x * blockDim.x + threadIdx.x;
    if (i < n) cur[i] = rp[i];
}

__global__ void fill_csr(const int* __restrict__ src, const int* __restrict__ dst,
                         int* __restrict__ cur, int* __restrict__ col, int E) {
    int i = blockIdx.x * blockDim.x + threadIdx.x;
    if (i < E) {
        int d = dst[i];
        int pos = atomicAdd(&cur[d], 1);
        col[pos] = src[i];
    }
}

// ---------------------------------------------------------------------------
// Fused kernel: CSR gather aggregation -> bf16 hi/lo smem X -> warp MMA GEMM
// (3-term split) -> bias + LeakyReLU + LayerNorm epilogue.
// 256 threads (8 warps). TM in {64, 32}.
// ---------------------------------------------------------------------------
__device__ __forceinline__ uint32_t s2u(const void* p) {
    return (uint32_t)__cvta_generic_to_shared(p);
}

__device__ __forceinline__ void ldsm_x4(uint32_t addr, uint32_t& r0, uint32_t& r1,
                                        uint32_t& r2, uint32_t& r3) {
    asm volatile("ldmatrix.sync.aligned.m8n8.x4.shared.b16 {%0,%1,%2,%3}, [%4];"
                 : "=r"(r0), "=r"(r1), "=r"(r2), "=r"(r3) : "r"(addr));
}

__device__ __forceinline__ void ldsm_x2t(uint32_t addr, uint32_t& r0, uint32_t& r1) {
    asm volatile("ldmatrix.sync.aligned.m8n8.x2.trans.shared.b16 {%0,%1}, [%2];"
                 : "=r"(r0), "=r"(r1) : "r"(addr));
}

__device__ __forceinline__ void mma_bf16(float* c, const uint32_t* a, const uint32_t* b) {
    asm volatile(
        "mma.sync.aligned.m16n8k16.row.col.f32.bf16.bf16.f32 "
        "{%0,%1,%2,%3}, {%4,%5,%6,%7}, {%8,%9}, {%0,%1,%2,%3};"
        : "+f"(c[0]), "+f"(c[1]), "+f"(c[2]), "+f"(c[3])
        : "r"(a[0]), "r"(a[1]), "r"(a[2]), "r"(a[3]), "r"(b[0]), "r"(b[1]));
}

template <int TM>
__global__ void __launch_bounds__(256)
fused_layer(const int* __restrict__ rpA, const int* __restrict__ rpB,
            const int* __restrict__ colAll,
            const float* __restrict__ hA, const float* __restrict__ invA,
            const float* __restrict__ hB, const float* __restrict__ invB,
            const __nv_bfloat16* __restrict__ WAhi, const __nv_bfloat16* __restrict__ WAlo,
            const __nv_bfloat16* __restrict__ WBhi, const __nv_bfloat16* __restrict__ WBlo,
            const float* __restrict__ bias,
            const float* __restrict__ lns, const float* __restrict__ lnb,
            float* __restrict__ out, int n) {
    constexpr int WARPS_M = TM / 32;         // 2 or 1
    constexpr int WARPS_N = 8 / WARPS_M;     // 4 or 8
    constexpr int WN = 128 / WARPS_N;        // 32 or 16
    constexpr int NT = WN / 8;               // n-tiles per warp: 4 or 2
    constexpr int XSTR = 264;                // bf16 elems per X row (pad)
    constexpr int WSTR = 136;                // bf16 elems per W smem row (pad)

    extern __shared__ char smem[];
    __nv_bfloat16* Xhi = reinterpret_cast<__nv_bfloat16*>(smem);
    __nv_bfloat16* Xlo = Xhi + TM * XSTR;
    __nv_bfloat16* Whs = Xlo + TM * XSTR;        // [64][WSTR]
    __nv_bfloat16* Wls = Whs + 64 * WSTR;
    float* spsum = reinterpret_cast<float*>(Wls + 64 * WSTR);   // [TM][WARPS_N]
    float* spsq  = spsum + TM * WARPS_N;
    float* stats = spsq + TM * WARPS_N;          // [TM][2]

    const int tid = threadIdx.x;
    const int lane = tid & 31;
    const int wid = tid >> 5;
    const int row0 = blockIdx.x * TM;

    const int warp_m = (wid % WARPS_M) * 32;
    const int nwid = wid / WARPS_M;
    const int warp_n = nwid * WN;

    // ---- aggregation: warp per row, lane owns 4 consecutive features ----
#pragma unroll
    for (int half = 0; half < 2; ++half) {
        const int* rp = half ? rpB : rpA;
        const float4* hp = reinterpret_cast<const float4*>(half ? hB : hA);
        const float* invp = half ? invB : invA;
        for (int r = wid; r < TM; r += 8) {
            int row = row0 + r;
            float4 a0 = make_float4(0.f, 0.f, 0.f, 0.f);
            float4 a1 = a0, a2 = a0, a3 = a0;
            float sc = 0.f;
            if (row < n) {
                int e = __ldg(rp + row);
                int eEnd = __ldg(rp + row + 1);
                sc = __ldg(invp + row);
                for (; e + 4 <= eEnd; e += 4) {
                    int s0 = __ldg(colAll + e);
                    int s1 = __ldg(colAll + e + 1);
                    int s2 = __ldg(colAll + e + 2);
                    int s3 = __ldg(colAll + e + 3);
                    float4 v0 = __ldg(hp + (size_t)s0 * 32 + lane);
                    float4 v1 = __ldg(hp + (size_t)s1 * 32 + lane);
                    float4 v2 = __ldg(hp + (size_t)s2 * 32 + lane);
                    float4 v3 = __ldg(hp + (size_t)s3 * 32 + lane);
                    a0.x += v0.x; a0.y += v0.y; a0.z += v0.z; a0.w += v0.w;
                    a1.x += v1.x; a1.y += v1.y; a1.z += v1.z; a1.w += v1.w;
                    a2.x += v2.x; a2.y += v2.y; a2.z += v2.z; a2.w += v2.w;
                    a3.x += v3.x; a3.y += v3.y; a3.z += v3.z; a3.w += v3.w;
                }
                for (; e < eEnd; ++e) {
                    int s = __ldg(colAll + e);
                    float4 v = __ldg(hp + (size_t)s * 32 + lane);
                    a0.x += v.x; a0.y += v.y; a0.z += v.z; a0.w += v.w;
                }
            }
            float vv[4] = {(a0.x + a1.x + a2.x + a3.x) * sc,
                           (a0.y + a1.y + a2.y + a3.y) * sc,
                           (a0.z + a1.z + a2.z + a3.z) * sc,
                           (a0.w + a1.w + a2.w + a3.w) * sc};
            __nv_bfloat16 hi4[4], lo4[4];
#pragma unroll
            for (int q = 0; q < 4; ++q) {
                __nv_bfloat16 h = __float2bfloat16_rn(vv[q]);
                hi4[q] = h;
                lo4[q] = __float2bfloat16_rn(vv[q] - __bfloat162float(h));
            }
            int xo = r * XSTR + half * 128 + lane * 4;
            *reinterpret_cast<uint2*>(Xhi + xo) = *reinterpret_cast<uint2*>(hi4);
            *reinterpret_cast<uint2*>(Xlo + xo) = *reinterpret_cast<uint2*>(lo4);
        }
    }

    // ---- precompute ldmatrix base addresses ----
    uint32_t xhi_base[2], xlo_base[2];
#pragma unroll
    for (int mi = 0; mi < 2; ++mi) {
        int row = warp_m + mi * 16 + (lane & 15);
        int koff = (lane >> 4) << 3;
        xhi_base[mi] = s2u(Xhi) + (row * XSTR + koff) * 2;
        xlo_base[mi] = s2u(Xlo) + (row * XSTR + koff) * 2;
    }
    uint32_t wh_base[NT], wl_base[NT];
#pragma unroll
    for (int ni = 0; ni < NT; ++ni) {
        int off = ((lane & 15) * WSTR + warp_n + ni * 8) * 2;
        wh_base[ni] = s2u(Whs) + off;
        wl_base[ni] = s2u(Wls) + off;
    }

    float acc[2][NT][4];
#pragma unroll
    for (int mi = 0; mi < 2; ++mi)
#pragma unroll
        for (int ni = 0; ni < NT; ++ni)
#pragma unroll
            for (int j = 0; j < 4; ++j) acc[mi][ni][j] = 0.f;

    // ---- GEMM: K = 256 in 4 tiles of 64 ----
#pragma unroll
    for (int kt = 0; kt < 4; ++kt) {
        const __nv_bfloat16* Wghi = (kt < 2) ? (WAhi + kt * 64 * 128) : (WBhi + (kt - 2) * 64 * 128);
        const __nv_bfloat16* Wglo = (kt < 2) ? (WAlo + kt * 64 * 128) : (WBlo + (kt - 2) * 64 * 128);
        __syncthreads();   // previous tile reads done (and agg done for kt=0)
        // copy 64x128 bf16 tile (hi & lo) into padded smem; 1024 16B-chunks each
#pragma unroll
        for (int c4 = 0; c4 < 4; ++c4) {
            int c = tid + c4 * 256;
            int wr = c >> 4;
            int wc = (c & 15) * 8;
            *reinterpret_cast<uint4*>(Whs + wr * WSTR + wc) =
                __ldg(reinterpret_cast<const uint4*>(Wghi + wr * 128 + wc));
            *reinterpret_cast<uint4*>(Wls + wr * WSTR + wc) =
                __ldg(reinterpret_cast<const uint4*>(Wglo + wr * 128 + wc));
        }
        __syncthreads();

#pragma unroll
        for (int ks = 0; ks < 4; ++ks) {
            int k0 = kt * 64 + ks * 16;   // global k into X
            uint32_t ah[2][4], al[2][4];
#pragma unroll
            for (int mi = 0; mi < 2; ++mi) {
                ldsm_x4(xhi_base[mi] + k0 * 2, ah[mi][0], ah[mi][1], ah[mi][2], ah[mi][3]);
                ldsm_x4(xlo_base[mi] + k0 * 2, al[mi][0], al[mi][1], al[mi][2], al[mi][3]);
            }
            uint32_t bh[NT][2], bl[NT][2];
#pragma unroll
            for (int ni = 0; ni < NT; ++ni) {
                ldsm_x2t(wh_base[ni] + (ks * 16) * WSTR * 2, bh[ni][0], bh[ni][1]);
                ldsm_x2t(wl_base[ni] + (ks * 16) * WSTR * 2, bl[ni][0], bl[ni][1]);
            }
#pragma unroll
            for (int mi = 0; mi < 2; ++mi)
#pragma unroll
                for (int ni = 0; ni < NT; ++ni) {
                    mma_bf16(acc[mi][ni], ah[mi], bh[ni]);
                    mma_bf16(acc[mi][ni], ah[mi], bl[ni]);
                    mma_bf16(acc[mi][ni], al[mi], bh[ni]);
                }
        }
    }

    // ---- epilogue: bias + leaky + LayerNorm ----
    float2 bias2[NT], lns2[NT], lnb2[NT];
#pragma unroll
    for (int ni = 0; ni < NT; ++ni) {
        int col = warp_n + ni * 8 + (lane & 3) * 2;
        bias2[ni] = *reinterpret_cast<const float2*>(bias + col);
        lns2[ni] = *reinterpret_cast<const float2*>(lns + col);
        lnb2[ni] = *reinterpret_cast<const float2*>(lnb + col);
    }

#pragma unroll
    for (int mi = 0; mi < 2; ++mi)
#pragma unroll
        for (int rh = 0; rh < 2; ++rh) {
            float s = 0.f, q = 0.f;
#pragma unroll
            for (int ni = 0; ni < NT; ++ni) {
                float v0 = acc[mi][ni][rh * 2 + 0] + bias2[ni].x;
                float v1 = acc[mi][ni][rh * 2 + 1] + bias2[ni].y;
                v0 = (v0 >= 0.f) ? v0 : 0.05f * v0;
                v1 = (v1 >= 0.f) ? v1 : 0.05f * v1;
                acc[mi][ni][rh * 2 + 0] = v0;
                acc[mi][ni][rh * 2 + 1] = v1;
                s += v0 + v1;
                q += v0 * v0 + v1 * v1;
            }
#pragma unroll
            for (int o = 1; o < 4; o <<= 1) {
                s += __shfl_xor_sync(0xffffffffu, s, o);
                q += __shfl_xor_sync(0xffffffffu, q, o);
            }
            if ((lane & 3) == 0) {
                int rl = warp_m + mi * 16 + (lane >> 2) + rh * 8;
                spsum[rl * WARPS_N + nwid] = s;
                spsq[rl * WARPS_N + nwid] = q;
            }
        }
    __syncthreads();

    if (tid < TM) {
        float s = 0.f, q = 0.f;
#pragma unroll
        for (int i = 0; i < WARPS_N; ++i) {
            s += spsum[tid * WARPS_N + i];
            q += spsq[tid * WARPS_N + i];
        }
        float mean = s * (1.f / 128.f);
        float var = q * (1.f / 128.f) - mean * mean;
        stats[tid * 2] = mean;
        stats[tid * 2 + 1] = rsqrtf(var + 1e-5f);
    }
    __syncthreads();

#pragma unroll
    for (int mi = 0; mi < 2; ++mi)
#pragma unroll
        for (int rh = 0; rh < 2; ++rh) {
            int rl = warp_m + mi * 16 + (lane >> 2) + rh * 8;
            int row = row0 + rl;
            if (row < n) {
                float mean = stats[rl * 2];
                float rstd = stats[rl * 2 + 1];
#pragma unroll
                for (int ni = 0; ni < NT; ++ni) {
                    int col = warp_n + ni * 8 + (lane & 3) * 2;
                    float y0 = (acc[mi][ni][rh * 2 + 0] - mean) * rstd * lns2[ni].x + lnb2[ni].x;
                    float y1 = (acc[mi][ni][rh * 2 + 1] - mean) * rstd * lns2[ni].y + lnb2[ni].y;
                    *reinterpret_cast<float2*>(out + (size_t)row * 128 + col) =
                        make_float2(y0, y1);
                }
            }
        }
}

// ---------------------------------------------------------------------------
extern "C" void kernel_launch(void* const* d_in, const int* in_sizes, int n_in,
                              void* d_out, int out_size) {
    const float* h_cell = (const float*)d_in[0];
    const float* h_gene = (const float*)d_in[1];
    const int* src_cg = (const int*)d_in[2];
    const int* dst_cg = (const int*)d_in[3];
    const int* src_gc = (const int*)d_in[4];
    const int* dst_gc = (const int*)d_in[5];
    const int* src_cc = (const int*)d_in[6];
    const int* dst_cc = (const int*)d_in[7];
    const int* src_gg = (const int*)d_in[8];
    const int* dst_gg = (const int*)d_in[9];
    const float* W_cg = (const float*)d_in[10];
    const float* W_gc = (const float*)d_in[11];
    const float* W_cc = (const float*)d_in[12];
    const float* W_gg = (const float*)d_in[13];
    const float* b_cell = (const float*)d_in[14];
    const float* b_gene = (const float*)d_in[15];
    const float* ln_s_cell = (const float*)d_in[16];
    const float* ln_b_cell = (const float*)d_in[17];
    const float* ln_s_gene = (const float*)d_in[18];
    const float* ln_b_gene = (const float*)d_in[19];
    float* out = (float*)d_out;

    int *deg, *cur, *rp, *col, *bsum, *bscan;
    float *inv, *hc1, *hg1;
    __nv_bfloat16 *Whi, *Wlo;
    cudaGetSymbolAddress((void**)&deg, g_deg);
    cudaGetSymbolAddress((void**)&cur, g_cur);
    cudaGetSymbolAddress((void**)&inv, g_inv);
    cudaGetSymbolAddress((void**)&rp, g_rp);
    cudaGetSymbolAddress((void**)&col, g_col);
    cudaGetSymbolAddress((void**)&bsum, g_bsum);
    cudaGetSymbolAddress((void**)&bscan, g_bscan);
    cudaGetSymbolAddress((void**)&hc1, g_hc1);
    cudaGetSymbolAddress((void**)&hg1, g_hg1);
    cudaGetSymbolAddress((void**)&Whi, g_Whi);
    cudaGetSymbolAddress((void**)&Wlo, g_Wlo);

    __nv_bfloat16* Whi_gc = Whi + 0 * 16384;
    __nv_bfloat16* Whi_cc = Whi + 1 * 16384;
    __nv_bfloat16* Whi_cg = Whi + 2 * 16384;
    __nv_bfloat16* Whi_gg = Whi + 3 * 16384;
    __nv_bfloat16* Wlo_gc = Wlo + 0 * 16384;
    __nv_bfloat16* Wlo_cc = Wlo + 1 * 16384;
    __nv_bfloat16* Wlo_cg = Wlo + 2 * 16384;
    __nv_bfloat16* Wlo_gg = Wlo + 3 * 16384;

    // smem sizes
    const int SMEM_C = (64 * 264 * 2) * 2 + (64 * 136 * 2) * 2 +
                       (64 * 4 * 4) * 2 + 64 * 2 * 4;          // ~105 KB
    const int SMEM_G = (32 * 264 * 2) * 2 + (64 * 136 * 2) * 2 +
                       (32 * 8 * 4) * 2 + 32 * 2 * 4;          // ~71 KB
    cudaFuncSetAttribute(fused_layer<64>, cudaFuncAttributeMaxDynamicSharedMemorySize, SMEM_C);
    cudaFuncSetAttribute(fused_layer<32>, cudaFuncAttributeMaxDynamicSharedMemorySize, SMEM_G);

    // ---- weight split (once) ----
    convert_w<<<16, 1024>>>(W_gc, Whi_gc, Wlo_gc);
    convert_w<<<16, 1024>>>(W_cc, Whi_cc, Wlo_cc);
    convert_w<<<16, 1024>>>(W_cg, Whi_cg, Wlo_cg);
    convert_w<<<16, 1024>>>(W_gg, Whi_gg, Wlo_gg);

    // ---- CSR build over concatenated degree space ----
    zero_i<<<(NDEG + 255) / 256, 256>>>(deg, NDEG);
    count_deg<<<(E_GC + 255) / 256, 256>>>(dst_gc, deg + OFF_GC, E_GC);
    count_deg<<<(E_CC + 255) / 256, 256>>>(dst_cc, deg + OFF_CC, E_CC);
    count_deg<<<(E_CG + 255) / 256, 256>>>(dst_cg, deg + OFF_CG, E_CG);
    count_deg<<<(E_GG + 255) / 256, 256>>>(dst_gg, deg + OFF_GG, E_GG);
    make_inv<<<(NDEG + 255) / 256, 256>>>(NDEG);

    const int NB = (NDEG + 1023) / 1024;   // 211
    scan_part1<<<NB, 1024>>>(deg, bsum, NDEG);
    exscan_small<<<1, 1024>>>(bsum, bscan, NB);
    scan_part3<<<NB, 1024>>>(deg, bscan, rp, NDEG);

    init_cursor<<<(NDEG + 255) / 256, 256>>>(rp, cur, NDEG);
    fill_csr<<<(E_GC + 255) / 256, 256>>>(src_gc, dst_gc, cur + OFF_GC, col, E_GC);
    fill_csr<<<(E_CC + 255) / 256, 256>>>(src_cc, dst_cc, cur + OFF_CC, col, E_CC);
    fill_csr<<<(E_CG + 255) / 256, 256>>>(src_cg, dst_cg, cur + OFF_CG, col, E_CG);
    fill_csr<<<(E_GG + 255) / 256, 256>>>(src_gg, dst_gg, cur + OFF_GG, col, E_GG);

    auto run_layer = [&](const float* hc, const float* hg, float* oc, float* og) {
        fused_layer<64><<<(NCn + 63) / 64, 256, SMEM_C>>>(
            rp + OFF_GC, rp + OFF_CC, col,
            hg, inv + OFF_GC, hc, inv + OFF_CC,
            Whi_gc, Wlo_gc, Whi_cc, Wlo_cc,
            b_cell, ln_s_cell, ln_b_cell, oc, NCn);
        fused_layer<32><<<(NGn + 31) / 32, 256, SMEM_G>>>(
            rp + OFF_CG, rp + OFF_GG, col,
            hc, inv + OFF_CG, hg, inv + OFF_GG,
            Whi_cg, Wlo_cg, Whi_gg, Wlo_gg,
            b_gene, ln_s_gene, ln_b_gene, og, NGn);
    };

    run_layer(h_cell, h_gene, hc1, hg1);
    run_layer(hc1, hg1, out, out + (size_t)NCn * 128);

    (void)in_sizes; (void)n_in; (void)out_size;
}

// round 5
// speedup vs baseline: 3.6556x; 1.0030x over previous
#include <cuda_runtime.h>
#include <cuda_bf16.h>
#include <cstdint>

// ---------------------------------------------------------------------------
// HiddenRRGCN round 5: unified per-layer launch (cells+genes), per-half K
// processing for 3 CTAs/SM, fused CSR-build kernels.
// ---------------------------------------------------------------------------

static constexpr int NCn = 100000;
static constexpr int NGn = 8000;
static constexpr int E_CG = 1500000;
static constexpr int E_GC = 1500000;
static constexpr int E_CC = 1000000;
static constexpr int E_GG = 200000;
static constexpr int NDEG = 2 * NCn + 2 * NGn;
static constexpr int E_ALL = E_CG + E_GC + E_CC + E_GG;

static constexpr int OFF_GC = 0;
static constexpr int OFF_CC = NCn;
static constexpr int OFF_CG = 2 * NCn;
static constexpr int OFF_GG = 2 * NCn + NGn;

// segment order in fused edge kernels (matches rp offsets)
static constexpr int B1 = E_GC;
static constexpr int B2 = E_GC + E_CC;
static constexpr int B3 = E_GC + E_CC + E_CG;

// ---- static scratch -------------------------------------------------------
__device__ int   g_deg[NDEG];
__device__ float g_inv[NDEG];
__device__ int   g_cur[NDEG];
__device__ int   g_rp[NDEG + 1];
__device__ int   g_col[E_ALL];
__device__ int   g_bsum[256];
__device__ int   g_bscan[257];
__device__ __align__(16) float g_hc1[(size_t)NCn * 128];
__device__ __align__(16) float g_hg1[(size_t)NGn * 128];
__device__ __align__(16) __nv_bfloat16 g_Whi[4][128 * 128];  // gc, cc, cg, gg
__device__ __align__(16) __nv_bfloat16 g_Wlo[4][128 * 128];

// ---------------------------------------------------------------------------
__global__ void zero_i(int* __restrict__ p, int n) {
    int i = blockIdx.x * blockDim.x + threadIdx.x;
    if (i < n) p[i] = 0;
}

// fused degree count over all 4 relations
__global__ void count_deg_all(const int* __restrict__ dst_gc, const int* __restrict__ dst_cc,
                              const int* __restrict__ dst_cg, const int* __restrict__ dst_gg) {
    int i = blockIdx.x * blockDim.x + threadIdx.x;
    if (i >= E_ALL) return;
    int d, off;
    if (i < B1)      { d = dst_gc[i];      off = OFF_GC; }
    else if (i < B2) { d = dst_cc[i - B1]; off = OFF_CC; }
    else if (i < B3) { d = dst_cg[i - B2]; off = OFF_CG; }
    else             { d = dst_gg[i - B3]; off = OFF_GG; }
    atomicAdd(&g_deg[off + d], 1);
}

__global__ void make_inv(int n) {
    int i = blockIdx.x * blockDim.x + threadIdx.x;
    if (i < n) {
        int d = g_deg[i];
        g_inv[i] = 1.0f / (float)(d > 0 ? d : 1);
    }
}

// fused weight split: 4 matrices of 128x128
__global__ void convert_w_all(const float* __restrict__ W0, const float* __restrict__ W1,
                              const float* __restrict__ W2, const float* __restrict__ W3) {
    int i = blockIdx.x * blockDim.x + threadIdx.x;
    if (i >= 4 * 16384) return;
    int m = i >> 14;
    int j = i & 16383;
    const float* W = (m == 0) ? W0 : (m == 1) ? W1 : (m == 2) ? W2 : W3;
    float v = W[j];
    __nv_bfloat16 h = __float2bfloat16_rn(v);
    g_Whi[m][j] = h;
    g_Wlo[m][j] = __float2bfloat16_rn(v - __bfloat162float(h));
}

// ---- multi-block exclusive scan over g_deg -> g_rp ----
__global__ void scan_part1(const int* __restrict__ in, int* __restrict__ bsum, int n) {
    __shared__ int ws[32];
    int tid = threadIdx.x;
    int i = blockIdx.x * 1024 + tid;
    int v = (i < n) ? in[i] : 0;
#pragma unroll
    for (int o = 16; o > 0; o >>= 1) v += __shfl_xor_sync(0xffffffffu, v, o);
    if ((tid & 31) == 0) ws[tid >> 5] = v;
    __syncthreads();
    if (tid < 32) {
        int s = ws[tid];
#pragma unroll
        for (int o = 16; o > 0; o >>= 1) s += __shfl_xor_sync(0xffffffffu, s, o);
        if (tid == 0) bsum[blockIdx.x] = s;
    }
}

__global__ void exscan_small(const int* __restrict__ in, int* __restrict__ out, int n) {
    __shared__ int ws[32];
    int tid = threadIdx.x;
    int v = (tid < n) ? in[tid] : 0;
    int x = v;
#pragma unroll
    for (int o = 1; o < 32; o <<= 1) {
        int t = __shfl_up_sync(0xffffffffu, x, o);
        if ((tid & 31) >= o) x += t;
    }
    if ((tid & 31) == 31) ws[tid >> 5] = x;
    __syncthreads();
    if (tid < 32) {
        int s = ws[tid];
#pragma unroll
        for (int o = 1; o < 32; o <<= 1) {
            int t = __shfl_up_sync(0xffffffffu, s, o);
            if (tid >= o) s += t;
        }
        ws[tid] = s;
    }
    __syncthreads();
    int woff = (tid >= 32) ? ws[(tid >> 5) - 1] : 0;
    if (tid < n) out[tid] = x - v + woff;
    if (tid == n - 1) out[n] = x + woff;
}

__global__ void scan_part3(const int* __restrict__ in, const int* __restrict__ boff,
                           int* __restrict__ out, int n) {
    __shared__ int ws[32];
    int tid = threadIdx.x;
    int i = blockIdx.x * 1024 + tid;
    int v = (i < n) ? in[i] : 0;
    int x = v;
#pragma unroll
    for (int o = 1; o < 32; o <<= 1) {
        int t = __shfl_up_sync(0xffffffffu, x, o);
        if ((tid & 31) >= o) x += t;
    }
    if ((tid & 31) == 31) ws[tid >> 5] = x;
    __syncthreads();
    if (tid < 32) {
        int s = ws[tid];
#pragma unroll
        for (int o = 1; o < 32; o <<= 1) {
            int t = __shfl_up_sync(0xffffffffu, s, o);
            if (tid >= o) s += t;
        }
        ws[tid] = s;
    }
    __syncthreads();
    int woff = ((tid >> 5) > 0) ? ws[(tid >> 5) - 1] : 0;
    int excl = x - v + woff + boff[blockIdx.x];
    if (i < n) out[i] = excl;
    if (i == n - 1) out[n] = excl + v;
}

__global__ void init_cursor(const int* __restrict__ rp, int* __restrict__ cur, int n) {
    int i = blockIdx.x * blockDim.x + threadIdx.x;
    if (i < n) cur[i] = rp[i];
}

// fused CSR fill over all 4 relations
__global__ void fill_csr_all(const int* __restrict__ src_gc, const int* __restrict__ dst_gc,
                             const int* __restrict__ src_cc, const int* __restrict__ dst_cc,
                             const int* __restrict__ src_cg, const int* __restrict__ dst_cg,
                             const int* __restrict__ src_gg, const int* __restrict__ dst_gg) {
    int i = blockIdx.x * blockDim.x + threadIdx.x;
    if (i >= E_ALL) return;
    int s, d, off;
    if (i < B1)      { s = src_gc[i];      d = dst_gc[i];      off = OFF_GC; }
    else if (i < B2) { s = src_cc[i - B1]; d = dst_cc[i - B1]; off = OFF_CC; }
    else if (i < B3) { s = src_cg[i - B2]; d = dst_cg[i - B2]; off = OFF_CG; }
    else             { s = src_gg[i - B3]; d = dst_gg[i - B3]; off = OFF_GG; }
    int pos = atomicAdd(&g_cur[off + d], 1);
    g_col[pos] = s;
}

// ---------------------------------------------------------------------------
// Unified fused layer kernel. TM = 64, 256 threads, 8 warps.
// Per K-half: CSR-gather agg -> bf16 hi/lo X smem -> 2 W tiles of MMA.
// smem ~70.5 KB -> 3 CTAs/SM.
// ---------------------------------------------------------------------------
__device__ __forceinline__ uint32_t s2u(const void* p) {
    return (uint32_t)__cvta_generic_to_shared(p);
}

__device__ __forceinline__ void ldsm_x4(uint32_t addr, uint32_t& r0, uint32_t& r1,
                                        uint32_t& r2, uint32_t& r3) {
    asm volatile("ldmatrix.sync.aligned.m8n8.x4.shared.b16 {%0,%1,%2,%3}, [%4];"
                 : "=r"(r0), "=r"(r1), "=r"(r2), "=r"(r3) : "r"(addr));
}

__device__ __forceinline__ void ldsm_x2t(uint32_t addr, uint32_t& r0, uint32_t& r1) {
    asm volatile("ldmatrix.sync.aligned.m8n8.x2.trans.shared.b16 {%0,%1}, [%2];"
                 : "=r"(r0), "=r"(r1) : "r"(addr));
}

__device__ __forceinline__ void mma_bf16(float* c, const uint32_t* a, const uint32_t* b) {
    asm volatile(
        "mma.sync.aligned.m16n8k16.row.col.f32.bf16.bf16.f32 "
        "{%0,%1,%2,%3}, {%4,%5,%6,%7}, {%8,%9}, {%0,%1,%2,%3};"
        : "+f"(c[0]), "+f"(c[1]), "+f"(c[2]), "+f"(c[3])
        : "r"(a[0]), "r"(a[1]), "r"(a[2]), "r"(a[3]), "r"(b[0]), "r"(b[1]));
}

struct Side {
    const int* rpA; const int* rpB;
    const float* hA; const float* invA;
    const float* hB; const float* invB;
    const __nv_bfloat16 *WAhi, *WAlo, *WBhi, *WBlo;
    const float *bias, *lns, *lnb;
    float* out;
    int n;
};

static constexpr int TM = 64;
static constexpr int XSTR = 136;   // bf16 elems per X row (one K-half + pad)
static constexpr int WSTR = 136;
static constexpr int FUSED_SMEM =
    (TM * XSTR * 2) * 2 +     // Xhi, Xlo
    (64 * WSTR * 2) * 2 +     // Whs, Wls
    (TM * 4 * 4) * 2 +        // spsum, spsq
    TM * 2 * 4;               // stats

__global__ void __launch_bounds__(256, 3)
fused_layer(const Side cs, const Side gs, const int* __restrict__ colAll, int nCellBlocks) {
    // WARPS_M=2, WARPS_N=4, WN=32, NT=4
    constexpr int NT = 4;
    constexpr int WARPS_N = 4;

    extern __shared__ char smem[];
    __nv_bfloat16* Xhi = reinterpret_cast<__nv_bfloat16*>(smem);
    __nv_bfloat16* Xlo = Xhi + TM * XSTR;
    __nv_bfloat16* Whs = Xlo + TM * XSTR;
    __nv_bfloat16* Wls = Whs + 64 * WSTR;
    float* spsum = reinterpret_cast<float*>(Wls + 64 * WSTR);
    float* spsq  = spsum + TM * WARPS_N;
    float* stats = spsq + TM * WARPS_N;

    const bool isCell = (int)blockIdx.x < nCellBlocks;
    const Side* S = isCell ? &cs : &gs;
    const int blk = isCell ? blockIdx.x : (blockIdx.x - nCellBlocks);
    const int row0 = blk * TM;
    const int n = S->n;

    const int tid = threadIdx.x;
    const int lane = tid & 31;
    const int wid = tid >> 5;
    const int warp_m = (wid & 1) * 32;
    const int nwid = wid >> 1;
    const int warp_n = nwid * 32;

    // ldmatrix base addresses
    uint32_t xhi_base[2], xlo_base[2];
#pragma unroll
    for (int mi = 0; mi < 2; ++mi) {
        int row = warp_m + mi * 16 + (lane & 15);
        int koff = (lane >> 4) << 3;
        xhi_base[mi] = s2u(Xhi) + (row * XSTR + koff) * 2;
        xlo_base[mi] = s2u(Xlo) + (row * XSTR + koff) * 2;
    }
    uint32_t wh_base[NT], wl_base[NT];
#pragma unroll
    for (int ni = 0; ni < NT; ++ni) {
        int off = ((lane & 15) * WSTR + warp_n + ni * 8) * 2;
        wh_base[ni] = s2u(Whs) + off;
        wl_base[ni] = s2u(Wls) + off;
    }

    float acc[2][NT][4];
#pragma unroll
    for (int mi = 0; mi < 2; ++mi)
#pragma unroll
        for (int ni = 0; ni < NT; ++ni)
#pragma unroll
            for (int j = 0; j < 4; ++j) acc[mi][ni][j] = 0.f;

#pragma unroll
    for (int half = 0; half < 2; ++half) {
        const int* rp = half ? S->rpB : S->rpA;
        const float4* hp = reinterpret_cast<const float4*>(half ? S->hB : S->hA);
        const float* invp = half ? S->invB : S->invA;
        const __nv_bfloat16* Whig = half ? S->WBhi : S->WAhi;
        const __nv_bfloat16* Wlog = half ? S->WBlo : S->WAlo;

        __syncthreads();   // previous half's X reads complete

        // ---- aggregation into X (this half's K=128) ----
        for (int r = wid; r < TM; r += 8) {
            int row = row0 + r;
            float4 a0 = make_float4(0.f, 0.f, 0.f, 0.f);
            float4 a1 = a0, a2 = a0, a3 = a0;
            float sc = 0.f;
            if (row < n) {
                int e = __ldg(rp + row);
                int eEnd = __ldg(rp + row + 1);
                sc = __ldg(invp + row);
                for (; e + 4 <= eEnd; e += 4) {
                    int s0 = __ldg(colAll + e);
                    int s1 = __ldg(colAll + e + 1);
                    int s2 = __ldg(colAll + e + 2);
                    int s3 = __ldg(colAll + e + 3);
                    float4 v0 = __ldg(hp + (size_t)s0 * 32 + lane);
                    float4 v1 = __ldg(hp + (size_t)s1 * 32 + lane);
                    float4 v2 = __ldg(hp + (size_t)s2 * 32 + lane);
                    float4 v3 = __ldg(hp + (size_t)s3 * 32 + lane);
                    a0.x += v0.x; a0.y += v0.y; a0.z += v0.z; a0.w += v0.w;
                    a1.x += v1.x; a1.y += v1.y; a1.z += v1.z; a1.w += v1.w;
                    a2.x += v2.x; a2.y += v2.y; a2.z += v2.z; a2.w += v2.w;
                    a3.x += v3.x; a3.y += v3.y; a3.z += v3.z; a3.w += v3.w;
                }
                for (; e < eEnd; ++e) {
                    int s = __ldg(colAll + e);
                    float4 v = __ldg(hp + (size_t)s * 32 + lane);
                    a0.x += v.x; a0.y += v.y; a0.z += v.z; a0.w += v.w;
                }
            }
            float vv[4] = {(a0.x + a1.x + a2.x + a3.x) * sc,
                           (a0.y + a1.y + a2.y + a3.y) * sc,
                           (a0.z + a1.z + a2.z + a3.z) * sc,
                           (a0.w + a1.w + a2.w + a3.w) * sc};
            __nv_bfloat16 hi4[4], lo4[4];
#pragma unroll
            for (int q = 0; q < 4; ++q) {
                __nv_bfloat16 h = __float2bfloat16_rn(vv[q]);
                hi4[q] = h;
                lo4[q] = __float2bfloat16_rn(vv[q] - __bfloat162float(h));
            }
            int xo = r * XSTR + lane * 4;
            *reinterpret_cast<uint2*>(Xhi + xo) = *reinterpret_cast<uint2*>(hi4);
            *reinterpret_cast<uint2*>(Xlo + xo) = *reinterpret_cast<uint2*>(lo4);
        }

        // ---- GEMM: 2 W tiles of 64 K-rows ----
#pragma unroll
        for (int kt2 = 0; kt2 < 2; ++kt2) {
            const __nv_bfloat16* Wghi = Whig + kt2 * 64 * 128;
            const __nv_bfloat16* Wglo = Wlog + kt2 * 64 * 128;
            __syncthreads();   // X written (kt2=0) / prior W reads done
#pragma unroll
            for (int c4 = 0; c4 < 4; ++c4) {
                int c = tid + c4 * 256;
                int wr = c >> 4;
                int wc = (c & 15) * 8;
                *reinterpret_cast<uint4*>(Whs + wr * WSTR + wc) =
                    __ldg(reinterpret_cast<const uint4*>(Wghi + wr * 128 + wc));
                *reinterpret_cast<uint4*>(Wls + wr * WSTR + wc) =
                    __ldg(reinterpret_cast<const uint4*>(Wglo + wr * 128 + wc));
            }
            __syncthreads();

#pragma unroll
            for (int ks = 0; ks < 4; ++ks) {
                int k0 = kt2 * 64 + ks * 16;
                uint32_t ah[2][4], al[2][4];
#pragma unroll
                for (int mi = 0; mi < 2; ++mi) {
                    ldsm_x4(xhi_base[mi] + k0 * 2, ah[mi][0], ah[mi][1], ah[mi][2], ah[mi][3]);
                    ldsm_x4(xlo_base[mi] + k0 * 2, al[mi][0], al[mi][1], al[mi][2], al[mi][3]);
                }
#pragma unroll
                for (int ni = 0; ni < NT; ++ni) {
                    uint32_t bh[2], bl[2];
                    ldsm_x2t(wh_base[ni] + (ks * 16) * WSTR * 2, bh[0], bh[1]);
                    ldsm_x2t(wl_base[ni] + (ks * 16) * WSTR * 2, bl[0], bl[1]);
#pragma unroll
                    for (int mi = 0; mi < 2; ++mi) {
                        mma_bf16(acc[mi][ni], ah[mi], bh);
                        mma_bf16(acc[mi][ni], ah[mi], bl);
                        mma_bf16(acc[mi][ni], al[mi], bh);
                    }
                }
            }
        }
    }

    // ---- epilogue: bias + leaky + LayerNorm ----
    const float* bias = S->bias;
    const float* lns = S->lns;
    const float* lnb = S->lnb;
    float* out = S->out;

    float2 bias2[NT], lns2[NT], lnb2[NT];
#pragma unroll
    for (int ni = 0; ni < NT; ++ni) {
        int col = warp_n + ni * 8 + (lane & 3) * 2;
        bias2[ni] = *reinterpret_cast<const float2*>(bias + col);
        lns2[ni] = *reinterpret_cast<const float2*>(lns + col);
        lnb2[ni] = *reinterpret_cast<const float2*>(lnb + col);
    }

#pragma unroll
    for (int mi = 0; mi < 2; ++mi)
#pragma unroll
        for (int rh = 0; rh < 2; ++rh) {
            float s = 0.f, q = 0.f;
#pragma unroll
            for (int ni = 0; ni < NT; ++ni) {
                float v0 = acc[mi][ni][rh * 2 + 0] + bias2[ni].x;
                float v1 = acc[mi][ni][rh * 2 + 1] + bias2[ni].y;
                v0 = (v0 >= 0.f) ? v0 : 0.05f * v0;
                v1 = (v1 >= 0.f) ? v1 : 0.05f * v1;
                acc[mi][ni][rh * 2 + 0] = v0;
                acc[mi][ni][rh * 2 + 1] = v1;
                s += v0 + v1;
                q += v0 * v0 + v1 * v1;
            }
#pragma unroll
            for (int o = 1; o < 4; o <<= 1) {
                s += __shfl_xor_sync(0xffffffffu, s, o);
                q += __shfl_xor_sync(0xffffffffu, q, o);
            }
            if ((lane & 3) == 0) {
                int rl = warp_m + mi * 16 + (lane >> 2) + rh * 8;
                spsum[rl * WARPS_N + nwid] = s;
                spsq[rl * WARPS_N + nwid] = q;
            }
        }
    __syncthreads();

    if (tid < TM) {
        float s = 0.f, q = 0.f;
#pragma unroll
        for (int i = 0; i < WARPS_N; ++i) {
            s += spsum[tid * WARPS_N + i];
            q += spsq[tid * WARPS_N + i];
        }
        float mean = s * (1.f / 128.f);
        float var = q * (1.f / 128.f) - mean * mean;
        stats[tid * 2] = mean;
        stats[tid * 2 + 1] = rsqrtf(var + 1e-5f);
    }
    __syncthreads();

#pragma unroll
    for (int mi = 0; mi < 2; ++mi)
#pragma unroll
        for (int rh = 0; rh < 2; ++rh) {
            int rl = warp_m + mi * 16 + (lane >> 2) + rh * 8;
            int row = row0 + rl;
            if (row < n) {
                float mean = stats[rl * 2];
                float rstd = stats[rl * 2 + 1];
#pragma unroll
                for (int ni = 0; ni < NT; ++ni) {
                    int col = warp_n + ni * 8 + (lane & 3) * 2;
                    float y0 = (acc[mi][ni][rh * 2 + 0] - mean) * rstd * lns2[ni].x + lnb2[ni].x;
                    float y1 = (acc[mi][ni][rh * 2 + 1] - mean) * rstd * lns2[ni].y + lnb2[ni].y;
                    *reinterpret_cast<float2*>(out + (size_t)row * 128 + col) =
                        make_float2(y0, y1);
                }
            }
        }
}

// ---------------------------------------------------------------------------
extern "C" void kernel_launch(void* const* d_in, const int* in_sizes, int n_in,
                              void* d_out, int out_size) {
    const float* h_cell = (const float*)d_in[0];
    const float* h_gene = (const float*)d_in[1];
    const int* src_cg = (const int*)d_in[2];
    const int* dst_cg = (const int*)d_in[3];
    const int* src_gc = (const int*)d_in[4];
    const int* dst_gc = (const int*)d_in[5];
    const int* src_cc = (const int*)d_in[6];
    const int* dst_cc = (const int*)d_in[7];
    const int* src_gg = (const int*)d_in[8];
    const int* dst_gg = (const int*)d_in[9];
    const float* W_cg = (const float*)d_in[10];
    const float* W_gc = (const float*)d_in[11];
    const float* W_cc = (const float*)d_in[12];
    const float* W_gg = (const float*)d_in[13];
    const float* b_cell = (const float*)d_in[14];
    const float* b_gene = (const float*)d_in[15];
    const float* ln_s_cell = (const float*)d_in[16];
    const float* ln_b_cell = (const float*)d_in[17];
    const float* ln_s_gene = (const float*)d_in[18];
    const float* ln_b_gene = (const float*)d_in[19];
    float* out = (float*)d_out;

    int *deg, *rp, *col, *bsum, *bscan, *cur;
    float *inv, *hc1, *hg1;
    __nv_bfloat16 *Whi, *Wlo;
    cudaGetSymbolAddress((void**)&deg, g_deg);
    cudaGetSymbolAddress((void**)&rp, g_rp);
    cudaGetSymbolAddress((void**)&col, g_col);
    cudaGetSymbolAddress((void**)&bsum, g_bsum);
    cudaGetSymbolAddress((void**)&bscan, g_bscan);
    cudaGetSymbolAddress((void**)&cur, g_cur);
    cudaGetSymbolAddress((void**)&inv, g_inv);
    cudaGetSymbolAddress((void**)&hc1, g_hc1);
    cudaGetSymbolAddress((void**)&hg1, g_hg1);
    cudaGetSymbolAddress((void**)&Whi, g_Whi);
    cudaGetSymbolAddress((void**)&Wlo, g_Wlo);

    cudaFuncSetAttribute(fused_layer, cudaFuncAttributeMaxDynamicSharedMemorySize, FUSED_SMEM);

    // ---- setup ----
    convert_w_all<<<(4 * 16384 + 255) / 256, 256>>>(W_gc, W_cc, W_cg, W_gg);
    zero_i<<<(NDEG + 255) / 256, 256>>>(deg, NDEG);
    count_deg_all<<<(E_ALL + 255) / 256, 256>>>(dst_gc, dst_cc, dst_cg, dst_gg);
    make_inv<<<(NDEG + 255) / 256, 256>>>(NDEG);

    const int NB = (NDEG + 1023) / 1024;
    scan_part1<<<NB, 1024>>>(deg, bsum, NDEG);
    exscan_small<<<1, 1024>>>(bsum, bscan, NB);
    scan_part3<<<NB, 1024>>>(deg, bscan, rp, NDEG);

    init_cursor<<<(NDEG + 255) / 256, 256>>>(rp, cur, NDEG);
    fill_csr_all<<<(E_ALL + 255) / 256, 256>>>(src_gc, dst_gc, src_cc, dst_cc,
                                               src_cg, dst_cg, src_gg, dst_gg);

    const int nCellBlocks = (NCn + TM - 1) / TM;   // 1563
    const int nGeneBlocks = (NGn + TM - 1) / TM;   // 125

    auto run_layer = [&](const float* hc, const float* hg, float* oc, float* og) {
        Side cs, gs;
        cs.rpA = rp + OFF_GC; cs.rpB = rp + OFF_CC;
        cs.hA = hg; cs.invA = inv + OFF_GC;
        cs.hB = hc; cs.invB = inv + OFF_CC;
        cs.WAhi = Whi + 0 * 16384; cs.WAlo = Wlo + 0 * 16384;   // gc
        cs.WBhi = Whi + 1 * 16384; cs.WBlo = Wlo + 1 * 16384;   // cc
        cs.bias = b_cell; cs.lns = ln_s_cell; cs.lnb = ln_b_cell;
        cs.out = oc; cs.n = NCn;

        gs.rpA = rp + OFF_CG; gs.rpB = rp + OFF_GG;
        gs.hA = hc; gs.invA = inv + OFF_CG;
        gs.hB = hg; gs.invB = inv + OFF_GG;
        gs.WAhi = Whi + 2 * 16384; gs.WAlo = Wlo + 2 * 16384;   // cg
        gs.WBhi = Whi + 3 * 16384; gs.WBlo = Wlo + 3 * 16384;   // gg
        gs.bias = b_gene; gs.lns = ln_s_gene; gs.lnb = ln_b_gene;
        gs.out = og; gs.n = NGn;

        fused_layer<<<nCellBlocks + nGeneBlocks, 256, FUSED_SMEM>>>(cs, gs, col, nCellBlocks);
    };

    run_layer(h_cell, h_gene, hc1, hg1);
    run_layer(hc1, hg1, out, out + (size_t)NCn * 128);

    (void)in_sizes; (void)n_in; (void)out_size;
}

// round 6
// speedup vs baseline: 4.2290x; 1.1569x over previous
#include <cuda_runtime.h>
#include <cuda_bf16.h>
#include <cstdint>

// ---------------------------------------------------------------------------
// HiddenRRGCN round 6: predicated+pipelined gather loop (no scalar remainder,
// col prefetch), fused setup passes. MMA pipeline unchanged from R5.
// ---------------------------------------------------------------------------

static constexpr int NCn = 100000;
static constexpr int NGn = 8000;
static constexpr int E_CG = 1500000;
static constexpr int E_GC = 1500000;
static constexpr int E_CC = 1000000;
static constexpr int E_GG = 200000;
static constexpr int NDEG = 2 * NCn + 2 * NGn;
static constexpr int E_ALL = E_CG + E_GC + E_CC + E_GG;

static constexpr int OFF_GC = 0;
static constexpr int OFF_CC = NCn;
static constexpr int OFF_CG = 2 * NCn;
static constexpr int OFF_GG = 2 * NCn + NGn;

static constexpr int B1 = E_GC;
static constexpr int B2 = E_GC + E_CC;
static constexpr int B3 = E_GC + E_CC + E_CG;

// ---- static scratch -------------------------------------------------------
__device__ int   g_deg[NDEG];
__device__ float g_inv[NDEG];
__device__ int   g_cur[NDEG];
__device__ int   g_rp[NDEG + 1];
__device__ int   g_col[E_ALL];
__device__ int   g_bsum[256];
__device__ int   g_bscan[257];
__device__ __align__(16) float g_hc1[(size_t)NCn * 128];
__device__ __align__(16) float g_hg1[(size_t)NGn * 128];
__device__ __align__(16) __nv_bfloat16 g_Whi[4][128 * 128];  // gc, cc, cg, gg
__device__ __align__(16) __nv_bfloat16 g_Wlo[4][128 * 128];

// ---------------------------------------------------------------------------
__global__ void zero_i(int* __restrict__ p, int n) {
    int i = blockIdx.x * blockDim.x + threadIdx.x;
    if (i < n) p[i] = 0;
}

__global__ void count_deg_all(const int* __restrict__ dst_gc, const int* __restrict__ dst_cc,
                              const int* __restrict__ dst_cg, const int* __restrict__ dst_gg) {
    int i = blockIdx.x * blockDim.x + threadIdx.x;
    if (i >= E_ALL) return;
    int d, off;
    if (i < B1)      { d = dst_gc[i];      off = OFF_GC; }
    else if (i < B2) { d = dst_cc[i - B1]; off = OFF_CC; }
    else if (i < B3) { d = dst_cg[i - B2]; off = OFF_CG; }
    else             { d = dst_gg[i - B3]; off = OFF_GG; }
    atomicAdd(&g_deg[off + d], 1);
}

__global__ void convert_w_all(const float* __restrict__ W0, const float* __restrict__ W1,
                              const float* __restrict__ W2, const float* __restrict__ W3) {
    int i = blockIdx.x * blockDim.x + threadIdx.x;
    if (i >= 4 * 16384) return;
    int m = i >> 14;
    int j = i & 16383;
    const float* W = (m == 0) ? W0 : (m == 1) ? W1 : (m == 2) ? W2 : W3;
    float v = W[j];
    __nv_bfloat16 h = __float2bfloat16_rn(v);
    g_Whi[m][j] = h;
    g_Wlo[m][j] = __float2bfloat16_rn(v - __bfloat162float(h));
}

// ---- scan pass 1: per-block sums (also emits inv-degree) ----
__global__ void scan_part1(const int* __restrict__ in, int* __restrict__ bsum, int n) {
    __shared__ int ws[32];
    int tid = threadIdx.x;
    int i = blockIdx.x * 1024 + tid;
    int v = (i < n) ? in[i] : 0;
    if (i < n) g_inv[i] = 1.0f / (float)(v > 0 ? v : 1);
    int x = v;
#pragma unroll
    for (int o = 16; o > 0; o >>= 1) x += __shfl_xor_sync(0xffffffffu, x, o);
    if ((tid & 31) == 0) ws[tid >> 5] = x;
    __syncthreads();
    if (tid < 32) {
        int s = ws[tid];
#pragma unroll
        for (int o = 16; o > 0; o >>= 1) s += __shfl_xor_sync(0xffffffffu, s, o);
        if (tid == 0) bsum[blockIdx.x] = s;
    }
}

__global__ void exscan_small(const int* __restrict__ in, int* __restrict__ out, int n) {
    __shared__ int ws[32];
    int tid = threadIdx.x;
    int v = (tid < n) ? in[tid] : 0;
    int x = v;
#pragma unroll
    for (int o = 1; o < 32; o <<= 1) {
        int t = __shfl_up_sync(0xffffffffu, x, o);
        if ((tid & 31) >= o) x += t;
    }
    if ((tid & 31) == 31) ws[tid >> 5] = x;
    __syncthreads();
    if (tid < 32) {
        int s = ws[tid];
#pragma unroll
        for (int o = 1; o < 32; o <<= 1) {
            int t = __shfl_up_sync(0xffffffffu, s, o);
            if (tid >= o) s += t;
        }
        ws[tid] = s;
    }
    __syncthreads();
    int woff = (tid >= 32) ? ws[(tid >> 5) - 1] : 0;
    if (tid < n) out[tid] = x - v + woff;
    if (tid == n - 1) out[n] = x + woff;
}

// ---- scan pass 3: exclusive scan (also seeds the fill cursor) ----
__global__ void scan_part3(const int* __restrict__ in, const int* __restrict__ boff,
                           int* __restrict__ out, int n) {
    __shared__ int ws[32];
    int tid = threadIdx.x;
    int i = blockIdx.x * 1024 + tid;
    int v = (i < n) ? in[i] : 0;
    int x = v;
#pragma unroll
    for (int o = 1; o < 32; o <<= 1) {
        int t = __shfl_up_sync(0xffffffffu, x, o);
        if ((tid & 31) >= o) x += t;
    }
    if ((tid & 31) == 31) ws[tid >> 5] = x;
    __syncthreads();
    if (tid < 32) {
        int s = ws[tid];
#pragma unroll
        for (int o = 1; o < 32; o <<= 1) {
            int t = __shfl_up_sync(0xffffffffu, s, o);
            if (tid >= o) s += t;
        }
        ws[tid] = s;
    }
    __syncthreads();
    int woff = ((tid >> 5) > 0) ? ws[(tid >> 5) - 1] : 0;
    int excl = x - v + woff + boff[blockIdx.x];
    if (i < n) {
        out[i] = excl;
        g_cur[i] = excl;
    }
    if (i == n - 1) out[n] = excl + v;
}

__global__ void fill_csr_all(const int* __restrict__ src_gc, const int* __restrict__ dst_gc,
                             const int* __restrict__ src_cc, const int* __restrict__ dst_cc,
                             const int* __restrict__ src_cg, const int* __restrict__ dst_cg,
                             const int* __restrict__ src_gg, const int* __restrict__ dst_gg) {
    int i = blockIdx.x * blockDim.x + threadIdx.x;
    if (i >= E_ALL) return;
    int s, d, off;
    if (i < B1)      { s = src_gc[i];      d = dst_gc[i];      off = OFF_GC; }
    else if (i < B2) { s = src_cc[i - B1]; d = dst_cc[i - B1]; off = OFF_CC; }
    else if (i < B3) { s = src_cg[i - B2]; d = dst_cg[i - B2]; off = OFF_CG; }
    else             { s = src_gg[i - B3]; d = dst_gg[i - B3]; off = OFF_GG; }
    int pos = atomicAdd(&g_cur[off + d], 1);
    g_col[pos] = s;
}

// ---------------------------------------------------------------------------
__device__ __forceinline__ uint32_t s2u(const void* p) {
    return (uint32_t)__cvta_generic_to_shared(p);
}

__device__ __forceinline__ void ldsm_x4(uint32_t addr, uint32_t& r0, uint32_t& r1,
                                        uint32_t& r2, uint32_t& r3) {
    asm volatile("ldmatrix.sync.aligned.m8n8.x4.shared.b16 {%0,%1,%2,%3}, [%4];"
                 : "=r"(r0), "=r"(r1), "=r"(r2), "=r"(r3) : "r"(addr));
}

__device__ __forceinline__ void ldsm_x2t(uint32_t addr, uint32_t& r0, uint32_t& r1) {
    asm volatile("ldmatrix.sync.aligned.m8n8.x2.trans.shared.b16 {%0,%1}, [%2];"
                 : "=r"(r0), "=r"(r1) : "r"(addr));
}

__device__ __forceinline__ void mma_bf16(float* c, const uint32_t* a, const uint32_t* b) {
    asm volatile(
        "mma.sync.aligned.m16n8k16.row.col.f32.bf16.bf16.f32 "
        "{%0,%1,%2,%3}, {%4,%5,%6,%7}, {%8,%9}, {%0,%1,%2,%3};"
        : "+f"(c[0]), "+f"(c[1]), "+f"(c[2]), "+f"(c[3])
        : "r"(a[0]), "r"(a[1]), "r"(a[2]), "r"(a[3]), "r"(b[0]), "r"(b[1]));
}

struct Side {
    const int* rpA; const int* rpB;
    const float* hA; const float* invA;
    const float* hB; const float* invB;
    const __nv_bfloat16 *WAhi, *WAlo, *WBhi, *WBlo;
    const float *bias, *lns, *lnb;
    float* out;
    int n;
};

static constexpr int TM = 64;
static constexpr int XSTR = 136;
static constexpr int WSTR = 136;
static constexpr int FUSED_SMEM =
    (TM * XSTR * 2) * 2 +
    (64 * WSTR * 2) * 2 +
    (TM * 4 * 4) * 2 +
    TM * 2 * 4;

__global__ void __launch_bounds__(256, 3)
fused_layer(const Side cs, const Side gs, const int* __restrict__ colAll, int nCellBlocks) {
    constexpr int NT = 4;
    constexpr int WARPS_N = 4;

    extern __shared__ char smem[];
    __nv_bfloat16* Xhi = reinterpret_cast<__nv_bfloat16*>(smem);
    __nv_bfloat16* Xlo = Xhi + TM * XSTR;
    __nv_bfloat16* Whs = Xlo + TM * XSTR;
    __nv_bfloat16* Wls = Whs + 64 * WSTR;
    float* spsum = reinterpret_cast<float*>(Wls + 64 * WSTR);
    float* spsq  = spsum + TM * WARPS_N;
    float* stats = spsq + TM * WARPS_N;

    const bool isCell = (int)blockIdx.x < nCellBlocks;
    const Side* S = isCell ? &cs : &gs;
    const int blk = isCell ? blockIdx.x : (blockIdx.x - nCellBlocks);
    const int row0 = blk * TM;
    const int n = S->n;

    const int tid = threadIdx.x;
    const int lane = tid & 31;
    const int wid = tid >> 5;
    const int warp_m = (wid & 1) * 32;
    const int nwid = wid >> 1;
    const int warp_n = nwid * 32;

    uint32_t xhi_base[2], xlo_base[2];
#pragma unroll
    for (int mi = 0; mi < 2; ++mi) {
        int row = warp_m + mi * 16 + (lane & 15);
        int koff = (lane >> 4) << 3;
        xhi_base[mi] = s2u(Xhi) + (row * XSTR + koff) * 2;
        xlo_base[mi] = s2u(Xlo) + (row * XSTR + koff) * 2;
    }
    uint32_t wh_base[NT], wl_base[NT];
#pragma unroll
    for (int ni = 0; ni < NT; ++ni) {
        int off = ((lane & 15) * WSTR + warp_n + ni * 8) * 2;
        wh_base[ni] = s2u(Whs) + off;
        wl_base[ni] = s2u(Wls) + off;
    }

    float acc[2][NT][4];
#pragma unroll
    for (int mi = 0; mi < 2; ++mi)
#pragma unroll
        for (int ni = 0; ni < NT; ++ni)
#pragma unroll
            for (int j = 0; j < 4; ++j) acc[mi][ni][j] = 0.f;

#pragma unroll
    for (int half = 0; half < 2; ++half) {
        const int* rp = half ? S->rpB : S->rpA;
        const float4* hp = reinterpret_cast<const float4*>(half ? S->hB : S->hA);
        const float* invp = half ? S->invB : S->invA;
        const __nv_bfloat16* Whig = half ? S->WBhi : S->WAhi;
        const __nv_bfloat16* Wlog = half ? S->WBlo : S->WAlo;

        __syncthreads();   // previous half's X reads complete

        // ---- aggregation: predicated chunks of 4, cols software-pipelined ----
        for (int r = wid; r < TM; r += 8) {
            int row = row0 + r;
            float4 a0 = make_float4(0.f, 0.f, 0.f, 0.f);
            float4 a1 = a0, a2 = a0, a3 = a0;
            float sc = 0.f;
            if (row < n) {
                int e = __ldg(rp + row);
                const int eEnd = __ldg(rp + row + 1);
                sc = __ldg(invp + row);
                if (e < eEnd) {
                    const int last = eEnd - 1;
                    int s0 = __ldg(colAll + e);
                    int s1 = __ldg(colAll + min(e + 1, last));
                    int s2 = __ldg(colAll + min(e + 2, last));
                    int s3 = __ldg(colAll + min(e + 3, last));
                    while (e < eEnd) {
                        const int en = e + 4;
                        // feature gathers (warp-uniform predication, zero-fill)
                        float4 z = make_float4(0.f, 0.f, 0.f, 0.f);
                        float4 v0 = __ldg(hp + (size_t)s0 * 32 + lane);
                        float4 v1 = (e + 1 < eEnd) ? __ldg(hp + (size_t)s1 * 32 + lane) : z;
                        float4 v2 = (e + 2 < eEnd) ? __ldg(hp + (size_t)s2 * 32 + lane) : z;
                        float4 v3 = (e + 3 < eEnd) ? __ldg(hp + (size_t)s3 * 32 + lane) : z;
                        // prefetch next chunk's cols while gathers are in flight
                        if (en < eEnd) {
                            s0 = __ldg(colAll + en);
                            s1 = __ldg(colAll + min(en + 1, last));
                            s2 = __ldg(colAll + min(en + 2, last));
                            s3 = __ldg(colAll + min(en + 3, last));
                        }
                        a0.x += v0.x; a0.y += v0.y; a0.z += v0.z; a0.w += v0.w;
                        a1.x += v1.x; a1.y += v1.y; a1.z += v1.z; a1.w += v1.w;
                        a2.x += v2.x; a2.y += v2.y; a2.z += v2.z; a2.w += v2.w;
                        a3.x += v3.x; a3.y += v3.y; a3.z += v3.z; a3.w += v3.w;
                        e = en;
                    }
                }
            }
            float vv[4] = {(a0.x + a1.x + a2.x + a3.x) * sc,
                           (a0.y + a1.y + a2.y + a3.y) * sc,
                           (a0.z + a1.z + a2.z + a3.z) * sc,
                           (a0.w + a1.w + a2.w + a3.w) * sc};
            __nv_bfloat16 hi4[4], lo4[4];
#pragma unroll
            for (int q = 0; q < 4; ++q) {
                __nv_bfloat16 h = __float2bfloat16_rn(vv[q]);
                hi4[q] = h;
                lo4[q] = __float2bfloat16_rn(vv[q] - __bfloat162float(h));
            }
            int xo = r * XSTR + lane * 4;
            *reinterpret_cast<uint2*>(Xhi + xo) = *reinterpret_cast<uint2*>(hi4);
            *reinterpret_cast<uint2*>(Xlo + xo) = *reinterpret_cast<uint2*>(lo4);
        }

        // ---- GEMM: 2 W tiles of 64 K-rows ----
#pragma unroll
        for (int kt2 = 0; kt2 < 2; ++kt2) {
            const __nv_bfloat16* Wghi = Whig + kt2 * 64 * 128;
            const __nv_bfloat16* Wglo = Wlog + kt2 * 64 * 128;
            __syncthreads();
#pragma unroll
            for (int c4 = 0; c4 < 4; ++c4) {
                int c = tid + c4 * 256;
                int wr = c >> 4;
                int wc = (c & 15) * 8;
                *reinterpret_cast<uint4*>(Whs + wr * WSTR + wc) =
                    __ldg(reinterpret_cast<const uint4*>(Wghi + wr * 128 + wc));
                *reinterpret_cast<uint4*>(Wls + wr * WSTR + wc) =
                    __ldg(reinterpret_cast<const uint4*>(Wglo + wr * 128 + wc));
            }
            __syncthreads();

#pragma unroll
            for (int ks = 0; ks < 4; ++ks) {
                int k0 = kt2 * 64 + ks * 16;
                uint32_t ah[2][4], al[2][4];
#pragma unroll
                for (int mi = 0; mi < 2; ++mi) {
                    ldsm_x4(xhi_base[mi] + k0 * 2, ah[mi][0], ah[mi][1], ah[mi][2], ah[mi][3]);
                    ldsm_x4(xlo_base[mi] + k0 * 2, al[mi][0], al[mi][1], al[mi][2], al[mi][3]);
                }
#pragma unroll
                for (int ni = 0; ni < NT; ++ni) {
                    uint32_t bh[2], bl[2];
                    ldsm_x2t(wh_base[ni] + (ks * 16) * WSTR * 2, bh[0], bh[1]);
                    ldsm_x2t(wl_base[ni] + (ks * 16) * WSTR * 2, bl[0], bl[1]);
#pragma unroll
                    for (int mi = 0; mi < 2; ++mi) {
                        mma_bf16(acc[mi][ni], ah[mi], bh);
                        mma_bf16(acc[mi][ni], ah[mi], bl);
                        mma_bf16(acc[mi][ni], al[mi], bh);
                    }
                }
            }
        }
    }

    // ---- epilogue ----
    const float* bias = S->bias;
    const float* lns = S->lns;
    const float* lnb = S->lnb;
    float* out = S->out;

    float2 bias2[NT], lns2[NT], lnb2[NT];
#pragma unroll
    for (int ni = 0; ni < NT; ++ni) {
        int col = warp_n + ni * 8 + (lane & 3) * 2;
        bias2[ni] = *reinterpret_cast<const float2*>(bias + col);
        lns2[ni] = *reinterpret_cast<const float2*>(lns + col);
        lnb2[ni] = *reinterpret_cast<const float2*>(lnb + col);
    }

#pragma unroll
    for (int mi = 0; mi < 2; ++mi)
#pragma unroll
        for (int rh = 0; rh < 2; ++rh) {
            float s = 0.f, q = 0.f;
#pragma unroll
            for (int ni = 0; ni < NT; ++ni) {
                float v0 = acc[mi][ni][rh * 2 + 0] + bias2[ni].x;
                float v1 = acc[mi][ni][rh * 2 + 1] + bias2[ni].y;
                v0 = (v0 >= 0.f) ? v0 : 0.05f * v0;
                v1 = (v1 >= 0.f) ? v1 : 0.05f * v1;
                acc[mi][ni][rh * 2 + 0] = v0;
                acc[mi][ni][rh * 2 + 1] = v1;
                s += v0 + v1;
                q += v0 * v0 + v1 * v1;
            }
#pragma unroll
            for (int o = 1; o < 4; o <<= 1) {
                s += __shfl_xor_sync(0xffffffffu, s, o);
                q += __shfl_xor_sync(0xffffffffu, q, o);
            }
            if ((lane & 3) == 0) {
                int rl = warp_m + mi * 16 + (lane >> 2) + rh * 8;
                spsum[rl * WARPS_N + nwid] = s;
                spsq[rl * WARPS_N + nwid] = q;
            }
        }
    __syncthreads();

    if (tid < TM) {
        float s = 0.f, q = 0.f;
#pragma unroll
        for (int i = 0; i < WARPS_N; ++i) {
            s += spsum[tid * WARPS_N + i];
            q += spsq[tid * WARPS_N + i];
        }
        float mean = s * (1.f / 128.f);
        float var = q * (1.f / 128.f) - mean * mean;
        stats[tid * 2] = mean;
        stats[tid * 2 + 1] = rsqrtf(var + 1e-5f);
    }
    __syncthreads();

#pragma unroll
    for (int mi = 0; mi < 2; ++mi)
#pragma unroll
        for (int rh = 0; rh < 2; ++rh) {
            int rl = warp_m + mi * 16 + (lane >> 2) + rh * 8;
            int row = row0 + rl;
            if (row < n) {
                float mean = stats[rl * 2];
                float rstd = stats[rl * 2 + 1];
#pragma unroll
                for (int ni = 0; ni < NT; ++ni) {
                    int col = warp_n + ni * 8 + (lane & 3) * 2;
                    float y0 = (acc[mi][ni][rh * 2 + 0] - mean) * rstd * lns2[ni].x + lnb2[ni].x;
                    float y1 = (acc[mi][ni][rh * 2 + 1] - mean) * rstd * lns2[ni].y + lnb2[ni].y;
                    *reinterpret_cast<float2*>(out + (size_t)row * 128 + col) =
                        make_float2(y0, y1);
                }
            }
        }
}

// ---------------------------------------------------------------------------
extern "C" void kernel_launch(void* const* d_in, const int* in_sizes, int n_in,
                              void* d_out, int out_size) {
    const float* h_cell = (const float*)d_in[0];
    const float* h_gene = (const float*)d_in[1];
    const int* src_cg = (const int*)d_in[2];
    const int* dst_cg = (const int*)d_in[3];
    const int* src_gc = (const int*)d_in[4];
    const int* dst_gc = (const int*)d_in[5];
    const int* src_cc = (const int*)d_in[6];
    const int* dst_cc = (const int*)d_in[7];
    const int* src_gg = (const int*)d_in[8];
    const int* dst_gg = (const int*)d_in[9];
    const float* W_cg = (const float*)d_in[10];
    const float* W_gc = (const float*)d_in[11];
    const float* W_cc = (const float*)d_in[12];
    const float* W_gg = (const float*)d_in[13];
    const float* b_cell = (const float*)d_in[14];
    const float* b_gene = (const float*)d_in[15];
    const float* ln_s_cell = (const float*)d_in[16];
    const float* ln_b_cell = (const float*)d_in[17];
    const float* ln_s_gene = (const float*)d_in[18];
    const float* ln_b_gene = (const float*)d_in[19];
    float* out = (float*)d_out;

    int *deg, *rp, *col, *bsum, *bscan;
    float *inv, *hc1, *hg1;
    __nv_bfloat16 *Whi, *Wlo;
    cudaGetSymbolAddress((void**)&deg, g_deg);
    cudaGetSymbolAddress((void**)&rp, g_rp);
    cudaGetSymbolAddress((void**)&col, g_col);
    cudaGetSymbolAddress((void**)&bsum, g_bsum);
    cudaGetSymbolAddress((void**)&bscan, g_bscan);
    cudaGetSymbolAddress((void**)&inv, g_inv);
    cudaGetSymbolAddress((void**)&hc1, g_hc1);
    cudaGetSymbolAddress((void**)&hg1, g_hg1);
    cudaGetSymbolAddress((void**)&Whi, g_Whi);
    cudaGetSymbolAddress((void**)&Wlo, g_Wlo);

    cudaFuncSetAttribute(fused_layer, cudaFuncAttributeMaxDynamicSharedMemorySize, FUSED_SMEM);

    // ---- setup ----
    convert_w_all<<<(4 * 16384 + 255) / 256, 256>>>(W_gc, W_cc, W_cg, W_gg);
    zero_i<<<(NDEG + 255) / 256, 256>>>(deg, NDEG);
    count_deg_all<<<(E_ALL + 255) / 256, 256>>>(dst_gc, dst_cc, dst_cg, dst_gg);

    const int NB = (NDEG + 1023) / 1024;
    scan_part1<<<NB, 1024>>>(deg, bsum, NDEG);          // also writes g_inv
    exscan_small<<<1, 1024>>>(bsum, bscan, NB);
    scan_part3<<<NB, 1024>>>(deg, bscan, rp, NDEG);     // also seeds g_cur

    fill_csr_all<<<(E_ALL + 255) / 256, 256>>>(src_gc, dst_gc, src_cc, dst_cc,
                                               src_cg, dst_cg, src_gg, dst_gg);

    const int nCellBlocks = (NCn + TM - 1) / TM;   // 1563
    const int nGeneBlocks = (NGn + TM - 1) / TM;   // 125

    auto run_layer = [&](const float* hc, const float* hg, float* oc, float* og) {
        Side cs, gs;
        cs.rpA = rp + OFF_GC; cs.rpB = rp + OFF_CC;
        cs.hA = hg; cs.invA = inv + OFF_GC;
        cs.hB = hc; cs.invB = inv + OFF_CC;
        cs.WAhi = Whi + 0 * 16384; cs.WAlo = Wlo + 0 * 16384;
        cs.WBhi = Whi + 1 * 16384; cs.WBlo = Wlo + 1 * 16384;
        cs.bias = b_cell; cs.lns = ln_s_cell; cs.lnb = ln_b_cell;
        cs.out = oc; cs.n = NCn;

        gs.rpA = rp + OFF_CG; gs.rpB = rp + OFF_GG;
        gs.hA = hc; gs.invA = inv + OFF_CG;
        gs.hB = hg; gs.invB = inv + OFF_GG;
        gs.WAhi = Whi + 2 * 16384; gs.WAlo = Wlo + 2 * 16384;
        gs.WBhi = Whi + 3 * 16384; gs.WBlo = Wlo + 3 * 16384;
        gs.bias = b_gene; gs.lns = ln_s_gene; gs.lnb = ln_b_gene;
        gs.out = og; gs.n = NGn;

        fused_layer<<<nCellBlocks + nGeneBlocks, 256, FUSED_SMEM>>>(cs, gs, col, nCellBlocks);
    };

    run_layer(h_cell, h_gene, hc1, hg1);
    run_layer(hc1, hg1, out, out + (size_t)NCn * 128);

    (void)in_sizes; (void)n_in; (void)out_size;
}